// round 9
// baseline (speedup 1.0000x reference)
#include <cuda_runtime.h>
#include <cstdint>

// GCN 2-layer, CSR-gather formulation (no float atomics, no inline PTX):
//   dinv[i] = rsqrt(1 + indeg[i])
//   layer:  g = dinv * (h @ W);  acc[i] = g[i] + sum_{e: dst(e)=i} g[src(e)]
//           h' = act(dinv[i]*acc[i] + b)
// edge_index dtype (int32 vs int64) detected at runtime; all indices clamped.

#define D_IN  128
#define D_HID 128
#define D_OUT 64
#define NMAX  100000
#define EMAX  1600000
#define SCAN_BLK 1024
#define NBLK_MAX 1024

// ---- scratch (device globals; 16B-aligned for float4 access) ----
__device__ __align__(16) float g_dinv[NMAX];
__device__ int   g_is64;
__device__ int   g_count[NMAX];
__device__ int   g_rowstart[NMAX + 1];
__device__ int   g_cursor[NMAX];
__device__ int   g_blocksum[NBLK_MAX];
__device__ int   g_srcidx[EMAX];
__device__ __align__(16) float g_g1[(size_t)NMAX * D_HID];
__device__ __align__(16) float g_acc1[(size_t)NMAX * D_HID];
__device__ __align__(16) float g_g2[(size_t)NMAX * D_OUT];

// ---------------- edge dtype detection ----------------
// If data is int64 with values < 2^31: all odd 32-bit words are 0.
// If data is int32 node indices: odd words are random indices, mostly nonzero.
__global__ void k_detect(const int* __restrict__ w, long long words32) {
    __shared__ int sm_nonzero;
    if (threadIdx.x == 0) sm_nonzero = 0;
    __syncthreads();
    long long limit = words32 < 8192 ? words32 : 8192;
    for (long long i = 1 + 2 * (long long)threadIdx.x; i < limit; i += 2 * blockDim.x)
        if (w[i] != 0) sm_nonzero = 1;   // benign race
    __syncthreads();
    if (threadIdx.x == 0) g_is64 = (sm_nonzero == 0) ? 1 : 0;
}

__device__ __forceinline__ void load_edge(const void* ei, long long E, long long e,
                                          int n, int& src, int& dst) {
    int s, d;
    if (g_is64) {
        const long long* p = (const long long*)ei;
        s = (int)p[e]; d = (int)p[E + e];
    } else {
        const int* p = (const int*)ei;
        s = p[e]; d = p[E + e];
    }
    src = min(max(s, 0), n - 1);
    dst = min(max(d, 0), n - 1);
}

// ---------------- CSR build ----------------
__global__ void k_zero(int n) {
    int i = blockIdx.x * blockDim.x + threadIdx.x;
    if (i < n) g_count[i] = 0;
}

__global__ void k_count(const void* __restrict__ ei, long long E, int n) {
    long long e = (long long)blockIdx.x * blockDim.x + threadIdx.x;
    if (e < E) {
        int src, dst;
        load_edge(ei, E, e, n, src, dst);
        atomicAdd(&g_count[dst], 1);
    }
}

// exclusive scan over n1 = n+1 entries (count[i] for i<n, else 0)
__global__ void k_scan1(int n1) {
    __shared__ int sm[SCAN_BLK];
    int gid = blockIdx.x * SCAN_BLK + threadIdx.x;
    int v = (gid < n1 - 1) ? g_count[gid] : 0;
    sm[threadIdx.x] = v;
    __syncthreads();
    for (int off = 1; off < SCAN_BLK; off <<= 1) {
        int t = (threadIdx.x >= off) ? sm[threadIdx.x - off] : 0;
        __syncthreads();
        sm[threadIdx.x] += t;
        __syncthreads();
    }
    if (gid < n1) g_rowstart[gid] = sm[threadIdx.x] - v;   // exclusive
    if (threadIdx.x == SCAN_BLK - 1) g_blocksum[blockIdx.x] = sm[threadIdx.x];
}

__global__ void k_scan2(int nb) {
    __shared__ int sm[SCAN_BLK];
    int v = (threadIdx.x < nb) ? g_blocksum[threadIdx.x] : 0;
    sm[threadIdx.x] = v;
    __syncthreads();
    for (int off = 1; off < SCAN_BLK; off <<= 1) {
        int t = (threadIdx.x >= off) ? sm[threadIdx.x - off] : 0;
        __syncthreads();
        sm[threadIdx.x] += t;
        __syncthreads();
    }
    if (threadIdx.x < nb) g_blocksum[threadIdx.x] = sm[threadIdx.x] - v;  // exclusive
}

__global__ void k_scan3(int n) {
    int gid = blockIdx.x * blockDim.x + threadIdx.x;
    if (gid <= n) {
        int r = g_rowstart[gid] + g_blocksum[gid / SCAN_BLK];
        g_rowstart[gid] = r;
        if (gid < n) {
            g_cursor[gid] = r;
            g_dinv[gid] = rsqrtf((float)g_count[gid] + 1.0f);  // +1 self-loop
        }
    }
}

__global__ void k_fill(const void* __restrict__ ei, long long E, int n) {
    long long e = (long long)blockIdx.x * blockDim.x + threadIdx.x;
    if (e < E) {
        int src, dst;
        load_edge(ei, E, e, n, src, dst);
        int pos = atomicAdd(&g_cursor[dst], 1);
        pos = min(max(pos, 0), EMAX - 1);
        g_srcidx[pos] = src;
    }
}

// ---------------- GEMM layer 1: g1 = dinv * (x @ W1) ----------------
// 64x64 output tile, K=128 in two 64-chunks. 256 threads, 4x4 per thread.
// smem: As[64][65] + Bs[64][64] = 32.6KB (< 48KB, no opt-in needed).
#define SMEM_G_FLOATS (64 * 65 + 64 * 64)

__global__ void k_gemm1(const float* __restrict__ x, const float* __restrict__ W, int n) {
    extern __shared__ float sm[];
    float* As = sm;              // [k][m] : 64 x 65
    float* Bs = sm + 64 * 65;    // [k][nc]: 64 x 64

    const int m0 = blockIdx.x * 64;
    const int n0 = blockIdx.y * 64;
    const int t  = threadIdx.x;
    const int ty = t >> 4, tx = t & 15;
    const int tm = ty * 4, tn = tx * 4;

    float acc[4][4];
#pragma unroll
    for (int i = 0; i < 4; i++)
#pragma unroll
        for (int j = 0; j < 4; j++) acc[i][j] = 0.0f;

    for (int kc = 0; kc < 128; kc += 64) {
        // load As: 64 m x 64 k, transposed into [k][m]
        for (int i = t; i < 64 * 64; i += 256) {
            int m = i >> 6, k = i & 63;
            int row = m0 + m;
            As[k * 65 + m] = (row < n) ? x[(size_t)row * D_IN + kc + k] : 0.0f;
        }
        // load Bs: W[kc+k][n0+nc], float4
        for (int i = t; i < (64 * 64) / 4; i += 256) {
            int k = i >> 4, nc4 = i & 15;
            ((float4*)Bs)[k * 16 + nc4] =
                *(const float4*)&W[(size_t)(kc + k) * D_HID + n0 + nc4 * 4];
        }
        __syncthreads();

#pragma unroll 8
        for (int k = 0; k < 64; k++) {
            float a[4];
#pragma unroll
            for (int i = 0; i < 4; i++) a[i] = As[k * 65 + tm + i];
            float4 b4 = *(const float4*)&Bs[k * 64 + tn];
            float b[4] = {b4.x, b4.y, b4.z, b4.w};
#pragma unroll
            for (int i = 0; i < 4; i++)
#pragma unroll
                for (int j = 0; j < 4; j++) acc[i][j] = fmaf(a[i], b[j], acc[i][j]);
        }
        __syncthreads();
    }

#pragma unroll
    for (int i = 0; i < 4; i++) {
        int row = m0 + tm + i;
        if (row < n) {
            float dv = g_dinv[row];
            *(float4*)&g_g1[(size_t)row * D_HID + n0 + tn] =
                make_float4(dv*acc[i][0], dv*acc[i][1], dv*acc[i][2], dv*acc[i][3]);
        }
    }
}

// ---------------- aggregation layer 1: acc1[i] = g1[i] + sum g1[src] ----------------
// one warp per node; lane owns one float4 (32*4 = 128 cols).
__global__ void k_agg1(int n) {
    int w = (blockIdx.x * blockDim.x + threadIdx.x) >> 5;
    int lane = threadIdx.x & 31;
    if (w >= n) return;
    const float4* base = (const float4*)g_g1;
    float4 a = base[(size_t)w * 32 + lane];
    int beg = g_rowstart[w], end = g_rowstart[w + 1];
    for (int j = beg; j < end; j++) {
        int s = g_srcidx[j];
        float4 v = base[(size_t)s * 32 + lane];
        a.x += v.x; a.y += v.y; a.z += v.z; a.w += v.w;
    }
    ((float4*)g_acc1)[(size_t)w * 32 + lane] = a;
}

// ---------------- GEMM layer 2: h = relu(dinv*acc1 + b1); g2 = dinv*(h @ W2) ----------------
__global__ void k_gemm2(const float* __restrict__ W, const float* __restrict__ b1, int n) {
    extern __shared__ float sm[];
    float* As = sm;              // [k][m] : 64 x 65
    float* Bs = sm + 64 * 65;    // [k][nc]: 64 x 64

    const int m0 = blockIdx.x * 64;
    const int t  = threadIdx.x;
    const int ty = t >> 4, tx = t & 15;
    const int tm = ty * 4, tn = tx * 4;

    float acc[4][4];
#pragma unroll
    for (int i = 0; i < 4; i++)
#pragma unroll
        for (int j = 0; j < 4; j++) acc[i][j] = 0.0f;

    for (int kc = 0; kc < 128; kc += 64) {
        for (int i = t; i < 64 * 64; i += 256) {
            int m = i >> 6, k = i & 63;
            int row = m0 + m;
            float v = 0.0f;
            if (row < n) {
                int kk = kc + k;
                v = fmaxf(fmaf(g_dinv[row], g_acc1[(size_t)row * D_HID + kk], b1[kk]), 0.0f);
            }
            As[k * 65 + m] = v;
        }
        for (int i = t; i < (64 * 64) / 4; i += 256) {
            int k = i >> 4, nc4 = i & 15;
            ((float4*)Bs)[k * 16 + nc4] =
                *(const float4*)&W[(size_t)(kc + k) * D_OUT + nc4 * 4];
        }
        __syncthreads();

#pragma unroll 8
        for (int k = 0; k < 64; k++) {
            float a[4];
#pragma unroll
            for (int i = 0; i < 4; i++) a[i] = As[k * 65 + tm + i];
            float4 b4 = *(const float4*)&Bs[k * 64 + tn];
            float b[4] = {b4.x, b4.y, b4.z, b4.w};
#pragma unroll
            for (int i = 0; i < 4; i++)
#pragma unroll
                for (int j = 0; j < 4; j++) acc[i][j] = fmaf(a[i], b[j], acc[i][j]);
        }
        __syncthreads();
    }

#pragma unroll
    for (int i = 0; i < 4; i++) {
        int row = m0 + tm + i;
        if (row < n) {
            float dv = g_dinv[row];
            *(float4*)&g_g2[(size_t)row * D_OUT + tn] =
                make_float4(dv*acc[i][0], dv*acc[i][1], dv*acc[i][2], dv*acc[i][3]);
        }
    }
}

// ---------------- aggregation layer 2 + epilogue: out = dinv*(g2[i] + sum g2[src]) + b2 ----------------
// half-warp per node; lane16 owns one float4 (16*4 = 64 cols).
__global__ void k_agg2(const float* __restrict__ b2, float* __restrict__ out, int n) {
    int hw = (blockIdx.x * blockDim.x + threadIdx.x) >> 4;
    int lane16 = threadIdx.x & 15;
    if (hw >= n) return;
    const float4* base = (const float4*)g_g2;
    float4 a = base[(size_t)hw * 16 + lane16];
    int beg = g_rowstart[hw], end = g_rowstart[hw + 1];
    for (int j = beg; j < end; j++) {
        int s = g_srcidx[j];
        float4 v = base[(size_t)s * 16 + lane16];
        a.x += v.x; a.y += v.y; a.z += v.z; a.w += v.w;
    }
    float dv = g_dinv[hw];
    float4 b = ((const float4*)b2)[lane16];
    ((float4*)out)[(size_t)hw * 16 + lane16] =
        make_float4(fmaf(dv, a.x, b.x), fmaf(dv, a.y, b.y),
                    fmaf(dv, a.z, b.z), fmaf(dv, a.w, b.w));
}

// ---------------- launch ----------------
extern "C" void kernel_launch(void* const* d_in, const int* in_sizes, int n_in,
                              void* d_out, int out_size) {
    // Identify inputs by element count (all distinct):
    //   x: N*128     edge_index: 2*E     W1: 16384  b1: 128  W2: 8192  b2: 64
    const float* x  = nullptr;
    const void*  ei = nullptr;
    const float* W1 = nullptr;
    const float* b1 = nullptr;
    const float* W2 = nullptr;
    const float* b2 = nullptr;
    int x_elems = 0, ei_elems = 0;

    int imax = 0, imax2 = -1;
    for (int i = 1; i < n_in; i++) if (in_sizes[i] > in_sizes[imax]) imax = i;
    for (int i = 0; i < n_in; i++) {
        if (i == imax) continue;
        if (imax2 < 0 || in_sizes[i] > in_sizes[imax2]) imax2 = i;
    }
    x  = (const float*)d_in[imax];  x_elems  = in_sizes[imax];
    ei = (const void*)d_in[imax2];  ei_elems = in_sizes[imax2];

    for (int i = 0; i < n_in; i++) {
        if (i == imax || i == imax2) continue;
        int s = in_sizes[i];
        if      (s == D_IN * D_HID)  W1 = (const float*)d_in[i];
        else if (s == D_HID)         b1 = (const float*)d_in[i];
        else if (s == D_HID * D_OUT) W2 = (const float*)d_in[i];
        else if (s == D_OUT)         b2 = (const float*)d_in[i];
    }

    float* out = (float*)d_out;
    const int n = x_elems / D_IN;
    const long long E = (long long)ei_elems / 2;   // element count / 2, dtype-independent
    const int n1 = n + 1;
    const int nb = (n1 + SCAN_BLK - 1) / SCAN_BLK;
    const int smemg = SMEM_G_FLOATS * 4;           // 32.6KB, no opt-in required

    // dtype detection, then CSR build
    k_detect<<<1, 256>>>((const int*)ei, (long long)ei_elems);
    k_zero <<<(n + 255) / 256, 256>>>(n);
    k_count<<<(int)((E + 255) / 256), 256>>>(ei, E, n);
    k_scan1<<<nb, SCAN_BLK>>>(n1);
    k_scan2<<<1, SCAN_BLK>>>(nb);
    k_scan3<<<(n1 + 255) / 256, 256>>>(n);
    k_fill <<<(int)((E + 255) / 256), 256>>>(ei, E, n);

    // layer 1
    dim3 grid1((n + 63) / 64, 2);
    k_gemm1<<<grid1, 256, smemg>>>(x, W1, n);
    k_agg1 <<<(n + 7) / 8, 256>>>(n);             // 8 warps/block, 1 node/warp

    // layer 2
    k_gemm2<<<(n + 63) / 64, 256, smemg>>>(W2, b1, n);
    k_agg2 <<<(n + 15) / 16, 256>>>(b2, out, n);  // 16 half-warps/block
}

// round 10
// speedup vs baseline: 1.2998x; 1.2998x over previous
#include <cuda_runtime.h>
#include <cstdint>

// GCN 2-layer, CSR-gather + tf32 tensor-core GEMMs.
//   dinv[i] = rsqrt(1 + indeg[i])
//   layer:  g = dinv * (h @ W);  acc[i] = g[i] + sum_{e: dst(e)=i} g[src(e)]
//           h' = act(dinv[i]*acc[i] + b)

#define D_IN  128
#define D_HID 128
#define D_OUT 64
#define NMAX  100000
#define EMAX  1600000
#define SCAN_BLK 1024
#define NBLK_MAX 1024

// ---- scratch ----
__device__ __align__(16) float g_dinv[NMAX];
__device__ int   g_is64;
__device__ int   g_count[NMAX];
__device__ int   g_rowstart[NMAX + 1];
__device__ int   g_cursor[NMAX];
__device__ int   g_blocksum[NBLK_MAX];
__device__ int   g_srcidx[EMAX];
__device__ __align__(16) float g_g1[(size_t)NMAX * D_HID];
__device__ __align__(16) float g_acc1[(size_t)NMAX * D_HID];
__device__ __align__(16) float g_g2[(size_t)NMAX * D_OUT];

// ---------------- tf32 helpers ----------------
__device__ __forceinline__ uint32_t f2tf32(float f) {
    uint32_t u;
    asm("cvt.rna.tf32.f32 %0, %1;" : "=r"(u) : "f"(f));
    return u;
}

__device__ __forceinline__ void mma_tf32(float* d, const uint32_t* a, const uint32_t* b) {
    asm volatile(
        "mma.sync.aligned.m16n8k8.row.col.f32.tf32.tf32.f32 "
        "{%0,%1,%2,%3},{%4,%5,%6,%7},{%8,%9},{%0,%1,%2,%3};"
        : "+f"(d[0]), "+f"(d[1]), "+f"(d[2]), "+f"(d[3])
        : "r"(a[0]), "r"(a[1]), "r"(a[2]), "r"(a[3]), "r"(b[0]), "r"(b[1]));
}

// ---------------- edge dtype detection ----------------
__global__ void k_detect(const int* __restrict__ w, long long words32) {
    __shared__ int sm_nonzero;
    if (threadIdx.x == 0) sm_nonzero = 0;
    __syncthreads();
    long long limit = words32 < 8192 ? words32 : 8192;
    for (long long i = 1 + 2 * (long long)threadIdx.x; i < limit; i += 2 * blockDim.x)
        if (w[i] != 0) sm_nonzero = 1;   // benign race
    __syncthreads();
    if (threadIdx.x == 0) g_is64 = (sm_nonzero == 0) ? 1 : 0;
}

__device__ __forceinline__ void load_edge(const void* ei, long long E, long long e,
                                          int n, int& src, int& dst) {
    int s, d;
    if (g_is64) {
        const long long* p = (const long long*)ei;
        s = (int)p[e]; d = (int)p[E + e];
    } else {
        const int* p = (const int*)ei;
        s = p[e]; d = p[E + e];
    }
    src = min(max(s, 0), n - 1);
    dst = min(max(d, 0), n - 1);
}

// ---------------- CSR build ----------------
__global__ void k_zero(int n) {
    int i = blockIdx.x * blockDim.x + threadIdx.x;
    if (i < n) g_count[i] = 0;
}

__global__ void k_count(const void* __restrict__ ei, long long E, int n) {
    long long e = (long long)blockIdx.x * blockDim.x + threadIdx.x;
    if (e < E) {
        int src, dst;
        load_edge(ei, E, e, n, src, dst);
        atomicAdd(&g_count[dst], 1);
    }
}

__global__ void k_scan1(int n1) {
    __shared__ int sm[SCAN_BLK];
    int gid = blockIdx.x * SCAN_BLK + threadIdx.x;
    int v = (gid < n1 - 1) ? g_count[gid] : 0;
    sm[threadIdx.x] = v;
    __syncthreads();
    for (int off = 1; off < SCAN_BLK; off <<= 1) {
        int t = (threadIdx.x >= off) ? sm[threadIdx.x - off] : 0;
        __syncthreads();
        sm[threadIdx.x] += t;
        __syncthreads();
    }
    if (gid < n1) g_rowstart[gid] = sm[threadIdx.x] - v;   // exclusive
    if (threadIdx.x == SCAN_BLK - 1) g_blocksum[blockIdx.x] = sm[threadIdx.x];
}

__global__ void k_scan2(int nb) {
    __shared__ int sm[SCAN_BLK];
    int v = (threadIdx.x < nb) ? g_blocksum[threadIdx.x] : 0;
    sm[threadIdx.x] = v;
    __syncthreads();
    for (int off = 1; off < SCAN_BLK; off <<= 1) {
        int t = (threadIdx.x >= off) ? sm[threadIdx.x - off] : 0;
        __syncthreads();
        sm[threadIdx.x] += t;
        __syncthreads();
    }
    if (threadIdx.x < nb) g_blocksum[threadIdx.x] = sm[threadIdx.x] - v;  // exclusive
}

__global__ void k_scan3(int n) {
    int gid = blockIdx.x * blockDim.x + threadIdx.x;
    if (gid <= n) {
        int r = g_rowstart[gid] + g_blocksum[gid / SCAN_BLK];
        g_rowstart[gid] = r;
        if (gid < n) {
            g_cursor[gid] = r;
            g_dinv[gid] = rsqrtf((float)g_count[gid] + 1.0f);  // +1 self-loop
        }
    }
}

__global__ void k_fill(const void* __restrict__ ei, long long E, int n) {
    long long e = (long long)blockIdx.x * blockDim.x + threadIdx.x;
    if (e < E) {
        int src, dst;
        load_edge(ei, E, e, n, src, dst);
        int pos = atomicAdd(&g_cursor[dst], 1);
        pos = min(max(pos, 0), EMAX - 1);
        g_srcidx[pos] = src;
    }
}

// ---------------- GEMM layer 1 (tf32 MMA): g1 = dinv * (x @ W1) ----------------
// BM=128, BN=128, K in 4 chunks of 32. 256 threads = 8 warps (2m x 4n),
// warp tile m64 n32. As[m][k] stride 36 (bank = lane+k, conflict-free),
// Bs[k][n] stride 132 (bank = 4k+n, conflict-free). smem 35KB static.
#define AS_STRIDE 36
#define BS1_STRIDE 132

__global__ void k_gemm1(const float* __restrict__ x, const float* __restrict__ W, int n) {
    __shared__ uint32_t As[128 * AS_STRIDE];
    __shared__ uint32_t Bs[32 * BS1_STRIDE];

    const int t = threadIdx.x;
    const int wid = t >> 5, lane = t & 31;
    const int wm = wid & 1, wn = wid >> 1;     // wm: 64-row half, wn: 32-col quarter
    const int m0 = blockIdx.x * 128;

    float acc[4][4][4];
#pragma unroll
    for (int mt = 0; mt < 4; mt++)
#pragma unroll
        for (int nt = 0; nt < 4; nt++)
#pragma unroll
            for (int r = 0; r < 4; r++) acc[mt][nt][r] = 0.0f;

    for (int kc = 0; kc < 128; kc += 32) {
        // fill As: 128 x 32, converted to tf32
        for (int i = t; i < 1024; i += 256) {
            int m = i >> 3, k4 = (i & 7) * 4;
            int row = m0 + m;
            float4 v = make_float4(0.f, 0.f, 0.f, 0.f);
            if (row < n) v = *(const float4*)&x[(size_t)row * D_IN + kc + k4];
            uint32_t* p = &As[m * AS_STRIDE + k4];
            p[0] = f2tf32(v.x); p[1] = f2tf32(v.y); p[2] = f2tf32(v.z); p[3] = f2tf32(v.w);
        }
        // fill Bs: 32 x 128
        for (int i = t; i < 1024; i += 256) {
            int k = i >> 5, n4 = (i & 31) * 4;
            float4 v = *(const float4*)&W[(size_t)(kc + k) * D_HID + n4];
            uint32_t* p = &Bs[k * BS1_STRIDE + n4];
            p[0] = f2tf32(v.x); p[1] = f2tf32(v.y); p[2] = f2tf32(v.z); p[3] = f2tf32(v.w);
        }
        __syncthreads();

#pragma unroll
        for (int ks = 0; ks < 4; ks++) {
            const int kb = ks * 8;
            uint32_t a[4][4], b[4][2];
            const int ar = wm * 64 + (lane >> 2);
            const int ac = kb + (lane & 3);
#pragma unroll
            for (int mt = 0; mt < 4; mt++) {
                a[mt][0] = As[(ar + mt * 16)     * AS_STRIDE + ac];
                a[mt][1] = As[(ar + mt * 16 + 8) * AS_STRIDE + ac];
                a[mt][2] = As[(ar + mt * 16)     * AS_STRIDE + ac + 4];
                a[mt][3] = As[(ar + mt * 16 + 8) * AS_STRIDE + ac + 4];
            }
            const int bn = wn * 32 + (lane >> 2);
            const int bk = kb + (lane & 3);
#pragma unroll
            for (int nt = 0; nt < 4; nt++) {
                b[nt][0] = Bs[bk       * BS1_STRIDE + bn + nt * 8];
                b[nt][1] = Bs[(bk + 4) * BS1_STRIDE + bn + nt * 8];
            }
#pragma unroll
            for (int mt = 0; mt < 4; mt++)
#pragma unroll
                for (int nt = 0; nt < 4; nt++) mma_tf32(acc[mt][nt], a[mt], b[nt]);
        }
        __syncthreads();
    }

    // epilogue: scale by dinv[row], store float2 per fragment pair
    const int rbase = m0 + wm * 64 + (lane >> 2);
    const int cbase = wn * 32 + (lane & 3) * 2;
#pragma unroll
    for (int mt = 0; mt < 4; mt++) {
#pragma unroll
        for (int half = 0; half < 2; half++) {
            int row = rbase + mt * 16 + half * 8;
            if (row < n) {
                float dv = g_dinv[row];
#pragma unroll
                for (int nt = 0; nt < 4; nt++) {
                    int col = cbase + nt * 8;
                    *(float2*)&g_g1[(size_t)row * D_HID + col] =
                        make_float2(dv * acc[mt][nt][2 * half],
                                    dv * acc[mt][nt][2 * half + 1]);
                }
            }
        }
    }
}

// ---------------- aggregation layer 1: acc1[i] = g1[i] + sum g1[src] ----------------
__global__ void k_agg1(int n) {
    int w = (blockIdx.x * blockDim.x + threadIdx.x) >> 5;
    int lane = threadIdx.x & 31;
    if (w >= n) return;
    const float4* base = (const float4*)g_g1;
    float4 a = base[(size_t)w * 32 + lane];
    int beg = g_rowstart[w], end = g_rowstart[w + 1];
    for (int j = beg; j < end; j++) {
        int s = g_srcidx[j];
        float4 v = base[(size_t)s * 32 + lane];
        a.x += v.x; a.y += v.y; a.z += v.z; a.w += v.w;
    }
    ((float4*)g_acc1)[(size_t)w * 32 + lane] = a;
}

// ---------------- GEMM layer 2 (tf32 MMA): h = relu(dinv*acc1 + b1); g2 = dinv*(h @ W2) ----------------
// BM=128, BN=64. 8 warps (2m x 4n), warp tile m64 n16 (2 n8-tiles).
#define BS2_STRIDE 68

__global__ void k_gemm2(const float* __restrict__ W, const float* __restrict__ b1, int n) {
    __shared__ uint32_t As[128 * AS_STRIDE];
    __shared__ uint32_t Bs[32 * BS2_STRIDE];

    const int t = threadIdx.x;
    const int wid = t >> 5, lane = t & 31;
    const int wm = wid & 1, wn = wid >> 1;     // wn: 16-col slice
    const int m0 = blockIdx.x * 128;

    float acc[4][2][4];
#pragma unroll
    for (int mt = 0; mt < 4; mt++)
#pragma unroll
        for (int nt = 0; nt < 2; nt++)
#pragma unroll
            for (int r = 0; r < 4; r++) acc[mt][nt][r] = 0.0f;

    for (int kc = 0; kc < 128; kc += 32) {
        // fill As with relu(dinv*acc1 + b1), tf32-converted
        for (int i = t; i < 1024; i += 256) {
            int m = i >> 3, k4 = (i & 7) * 4;
            int row = m0 + m;
            float4 v = make_float4(0.f, 0.f, 0.f, 0.f);
            if (row < n) {
                float dv = g_dinv[row];
                float4 a4 = *(const float4*)&g_acc1[(size_t)row * D_HID + kc + k4];
                float4 bb = *(const float4*)&b1[kc + k4];
                v = make_float4(fmaxf(fmaf(dv, a4.x, bb.x), 0.f),
                                fmaxf(fmaf(dv, a4.y, bb.y), 0.f),
                                fmaxf(fmaf(dv, a4.z, bb.z), 0.f),
                                fmaxf(fmaf(dv, a4.w, bb.w), 0.f));
            }
            uint32_t* p = &As[m * AS_STRIDE + k4];
            p[0] = f2tf32(v.x); p[1] = f2tf32(v.y); p[2] = f2tf32(v.z); p[3] = f2tf32(v.w);
        }
        // fill Bs: 32 x 64
        for (int i = t; i < 512; i += 256) {
            int k = i >> 4, n4 = (i & 15) * 4;
            float4 v = *(const float4*)&W[(size_t)(kc + k) * D_OUT + n4];
            uint32_t* p = &Bs[k * BS2_STRIDE + n4];
            p[0] = f2tf32(v.x); p[1] = f2tf32(v.y); p[2] = f2tf32(v.z); p[3] = f2tf32(v.w);
        }
        __syncthreads();

#pragma unroll
        for (int ks = 0; ks < 4; ks++) {
            const int kb = ks * 8;
            uint32_t a[4][4], b[2][2];
            const int ar = wm * 64 + (lane >> 2);
            const int ac = kb + (lane & 3);
#pragma unroll
            for (int mt = 0; mt < 4; mt++) {
                a[mt][0] = As[(ar + mt * 16)     * AS_STRIDE + ac];
                a[mt][1] = As[(ar + mt * 16 + 8) * AS_STRIDE + ac];
                a[mt][2] = As[(ar + mt * 16)     * AS_STRIDE + ac + 4];
                a[mt][3] = As[(ar + mt * 16 + 8) * AS_STRIDE + ac + 4];
            }
            const int bn = wn * 16 + (lane >> 2);
            const int bk = kb + (lane & 3);
#pragma unroll
            for (int nt = 0; nt < 2; nt++) {
                b[nt][0] = Bs[bk       * BS2_STRIDE + bn + nt * 8];
                b[nt][1] = Bs[(bk + 4) * BS2_STRIDE + bn + nt * 8];
            }
#pragma unroll
            for (int mt = 0; mt < 4; mt++)
#pragma unroll
                for (int nt = 0; nt < 2; nt++) mma_tf32(acc[mt][nt], a[mt], b[nt]);
        }
        __syncthreads();
    }

    const int rbase = m0 + wm * 64 + (lane >> 2);
    const int cbase = wn * 16 + (lane & 3) * 2;
#pragma unroll
    for (int mt = 0; mt < 4; mt++) {
#pragma unroll
        for (int half = 0; half < 2; half++) {
            int row = rbase + mt * 16 + half * 8;
            if (row < n) {
                float dv = g_dinv[row];
#pragma unroll
                for (int nt = 0; nt < 2; nt++) {
                    int col = cbase + nt * 8;
                    *(float2*)&g_g2[(size_t)row * D_OUT + col] =
                        make_float2(dv * acc[mt][nt][2 * half],
                                    dv * acc[mt][nt][2 * half + 1]);
                }
            }
        }
    }
}

// ---------------- aggregation layer 2 + epilogue ----------------
__global__ void k_agg2(const float* __restrict__ b2, float* __restrict__ out, int n) {
    int hw = (blockIdx.x * blockDim.x + threadIdx.x) >> 4;
    int lane16 = threadIdx.x & 15;
    if (hw >= n) return;
    const float4* base = (const float4*)g_g2;
    float4 a = base[(size_t)hw * 16 + lane16];
    int beg = g_rowstart[hw], end = g_rowstart[hw + 1];
    for (int j = beg; j < end; j++) {
        int s = g_srcidx[j];
        float4 v = base[(size_t)s * 16 + lane16];
        a.x += v.x; a.y += v.y; a.z += v.z; a.w += v.w;
    }
    float dv = g_dinv[hw];
    float4 b = ((const float4*)b2)[lane16];
    ((float4*)out)[(size_t)hw * 16 + lane16] =
        make_float4(fmaf(dv, a.x, b.x), fmaf(dv, a.y, b.y),
                    fmaf(dv, a.z, b.z), fmaf(dv, a.w, b.w));
}

// ---------------- launch ----------------
extern "C" void kernel_launch(void* const* d_in, const int* in_sizes, int n_in,
                              void* d_out, int out_size) {
    const float* x  = nullptr;
    const void*  ei = nullptr;
    const float* W1 = nullptr;
    const float* b1 = nullptr;
    const float* W2 = nullptr;
    const float* b2 = nullptr;
    int x_elems = 0, ei_elems = 0;

    int imax = 0, imax2 = -1;
    for (int i = 1; i < n_in; i++) if (in_sizes[i] > in_sizes[imax]) imax = i;
    for (int i = 0; i < n_in; i++) {
        if (i == imax) continue;
        if (imax2 < 0 || in_sizes[i] > in_sizes[imax2]) imax2 = i;
    }
    x  = (const float*)d_in[imax];  x_elems  = in_sizes[imax];
    ei = (const void*)d_in[imax2];  ei_elems = in_sizes[imax2];

    for (int i = 0; i < n_in; i++) {
        if (i == imax || i == imax2) continue;
        int s = in_sizes[i];
        if      (s == D_IN * D_HID)  W1 = (const float*)d_in[i];
        else if (s == D_HID)         b1 = (const float*)d_in[i];
        else if (s == D_HID * D_OUT) W2 = (const float*)d_in[i];
        else if (s == D_OUT)         b2 = (const float*)d_in[i];
    }

    float* out = (float*)d_out;
    const int n = x_elems / D_IN;
    const long long E = (long long)ei_elems / 2;
    const int n1 = n + 1;
    const int nb = (n1 + SCAN_BLK - 1) / SCAN_BLK;

    // dtype detection, then CSR build
    k_detect<<<1, 256>>>((const int*)ei, (long long)ei_elems);
    k_zero <<<(n + 255) / 256, 256>>>(n);
    k_count<<<(int)((E + 255) / 256), 256>>>(ei, E, n);
    k_scan1<<<nb, SCAN_BLK>>>(n1);
    k_scan2<<<1, SCAN_BLK>>>(nb);
    k_scan3<<<(n1 + 255) / 256, 256>>>(n);
    k_fill <<<(int)((E + 255) / 256), 256>>>(ei, E, n);

    // layer 1
    k_gemm1<<<(n + 127) / 128, 256>>>(x, W1, n);
    k_agg1 <<<(n + 7) / 8, 256>>>(n);             // 1 node/warp

    // layer 2
    k_gemm2<<<(n + 127) / 128, 256>>>(W2, b1, n);
    k_agg2 <<<(n + 15) / 16, 256>>>(b2, out, n);  // 1 node/half-warp
}

// round 11
// speedup vs baseline: 1.4447x; 1.1115x over previous
#include <cuda_runtime.h>
#include <cuda_fp16.h>
#include <cstdint>

// GCN 2-layer, CSR-gather + tf32 tensor-core GEMMs + fp16 gather tensors.
//   dinv[i] = rsqrt(1 + indeg[i])
//   layer:  g = dinv * (h @ W)            (g stored fp16)
//           acc[i] = g[i] + sum_{e: dst(e)=i} g[src(e)]   (fp32 accumulate)
//           h' = act(dinv[i]*acc[i] + b)

#define D_IN  128
#define D_HID 128
#define D_OUT 64
#define NMAX  100000
#define EMAX  1600000
#define SCAN_BLK 1024
#define NBLK_MAX 1024

// ---- scratch ----
__device__ __align__(16) float g_dinv[NMAX];
__device__ int   g_is64;
__device__ int   g_count[NMAX];
__device__ int   g_rowstart[NMAX + 1];
__device__ int   g_cursor[NMAX];
__device__ int   g_blocksum[NBLK_MAX];
__device__ int   g_srcidx[EMAX];
__device__ __align__(16) __half g_g1h[(size_t)NMAX * D_HID];   // fp16 gather tensor L1
__device__ __align__(16) float  g_acc1[(size_t)NMAX * D_HID];  // fp32 node-local
__device__ __align__(16) __half g_g2h[(size_t)NMAX * D_OUT];   // fp16 gather tensor L2

// ---------------- tf32 helpers ----------------
__device__ __forceinline__ uint32_t f2tf32(float f) {
    uint32_t u;
    asm("cvt.rna.tf32.f32 %0, %1;" : "=r"(u) : "f"(f));
    return u;
}

__device__ __forceinline__ void mma_tf32(float* d, const uint32_t* a, const uint32_t* b) {
    asm volatile(
        "mma.sync.aligned.m16n8k8.row.col.f32.tf32.tf32.f32 "
        "{%0,%1,%2,%3},{%4,%5,%6,%7},{%8,%9},{%0,%1,%2,%3};"
        : "+f"(d[0]), "+f"(d[1]), "+f"(d[2]), "+f"(d[3])
        : "r"(a[0]), "r"(a[1]), "r"(a[2]), "r"(a[3]), "r"(b[0]), "r"(b[1]));
}

// ---------------- edge dtype detection ----------------
__global__ void k_detect(const int* __restrict__ w, long long words32) {
    __shared__ int sm_nonzero;
    if (threadIdx.x == 0) sm_nonzero = 0;
    __syncthreads();
    long long limit = words32 < 8192 ? words32 : 8192;
    for (long long i = 1 + 2 * (long long)threadIdx.x; i < limit; i += 2 * blockDim.x)
        if (w[i] != 0) sm_nonzero = 1;   // benign race
    __syncthreads();
    if (threadIdx.x == 0) g_is64 = (sm_nonzero == 0) ? 1 : 0;
}

__device__ __forceinline__ void load_edge(const void* ei, long long E, long long e,
                                          int n, int& src, int& dst) {
    int s, d;
    if (g_is64) {
        const long long* p = (const long long*)ei;
        s = (int)p[e]; d = (int)p[E + e];
    } else {
        const int* p = (const int*)ei;
        s = p[e]; d = p[E + e];
    }
    src = min(max(s, 0), n - 1);
    dst = min(max(d, 0), n - 1);
}

// ---------------- CSR build ----------------
__global__ void k_zero(int n) {
    int i = blockIdx.x * blockDim.x + threadIdx.x;
    if (i < n) g_count[i] = 0;
}

__global__ void k_count(const void* __restrict__ ei, long long E, int n) {
    long long e = (long long)blockIdx.x * blockDim.x + threadIdx.x;
    if (e < E) {
        int src, dst;
        load_edge(ei, E, e, n, src, dst);
        atomicAdd(&g_count[dst], 1);
    }
}

__global__ void k_scan1(int n1) {
    __shared__ int sm[SCAN_BLK];
    int gid = blockIdx.x * SCAN_BLK + threadIdx.x;
    int v = (gid < n1 - 1) ? g_count[gid] : 0;
    sm[threadIdx.x] = v;
    __syncthreads();
    for (int off = 1; off < SCAN_BLK; off <<= 1) {
        int t = (threadIdx.x >= off) ? sm[threadIdx.x - off] : 0;
        __syncthreads();
        sm[threadIdx.x] += t;
        __syncthreads();
    }
    if (gid < n1) g_rowstart[gid] = sm[threadIdx.x] - v;   // exclusive
    if (threadIdx.x == SCAN_BLK - 1) g_blocksum[blockIdx.x] = sm[threadIdx.x];
}

__global__ void k_scan2(int nb) {
    __shared__ int sm[SCAN_BLK];
    int v = (threadIdx.x < nb) ? g_blocksum[threadIdx.x] : 0;
    sm[threadIdx.x] = v;
    __syncthreads();
    for (int off = 1; off < SCAN_BLK; off <<= 1) {
        int t = (threadIdx.x >= off) ? sm[threadIdx.x - off] : 0;
        __syncthreads();
        sm[threadIdx.x] += t;
        __syncthreads();
    }
    if (threadIdx.x < nb) g_blocksum[threadIdx.x] = sm[threadIdx.x] - v;  // exclusive
}

__global__ void k_scan3(int n) {
    int gid = blockIdx.x * blockDim.x + threadIdx.x;
    if (gid <= n) {
        int r = g_rowstart[gid] + g_blocksum[gid / SCAN_BLK];
        g_rowstart[gid] = r;
        if (gid < n) {
            g_cursor[gid] = r;
            g_dinv[gid] = rsqrtf((float)g_count[gid] + 1.0f);  // +1 self-loop
        }
    }
}

__global__ void k_fill(const void* __restrict__ ei, long long E, int n) {
    long long e = (long long)blockIdx.x * blockDim.x + threadIdx.x;
    if (e < E) {
        int src, dst;
        load_edge(ei, E, e, n, src, dst);
        int pos = atomicAdd(&g_cursor[dst], 1);
        pos = min(max(pos, 0), EMAX - 1);
        g_srcidx[pos] = src;
    }
}

// ---------------- GEMM layer 1 (tf32 MMA): g1h = fp16(dinv * (x @ W1)) ----------------
// BM=128, BN=128, K in 4 chunks of 32. 8 warps (2m x 4n), warp tile m64 n32.
#define AS_STRIDE 36
#define BS1_STRIDE 132

__global__ void k_gemm1(const float* __restrict__ x, const float* __restrict__ W, int n) {
    __shared__ uint32_t As[128 * AS_STRIDE];
    __shared__ uint32_t Bs[32 * BS1_STRIDE];

    const int t = threadIdx.x;
    const int wid = t >> 5, lane = t & 31;
    const int wm = wid & 1, wn = wid >> 1;
    const int m0 = blockIdx.x * 128;

    float acc[4][4][4];
#pragma unroll
    for (int mt = 0; mt < 4; mt++)
#pragma unroll
        for (int nt = 0; nt < 4; nt++)
#pragma unroll
            for (int r = 0; r < 4; r++) acc[mt][nt][r] = 0.0f;

    for (int kc = 0; kc < 128; kc += 32) {
        for (int i = t; i < 1024; i += 256) {
            int m = i >> 3, k4 = (i & 7) * 4;
            int row = m0 + m;
            float4 v = make_float4(0.f, 0.f, 0.f, 0.f);
            if (row < n) v = *(const float4*)&x[(size_t)row * D_IN + kc + k4];
            uint32_t* p = &As[m * AS_STRIDE + k4];
            p[0] = f2tf32(v.x); p[1] = f2tf32(v.y); p[2] = f2tf32(v.z); p[3] = f2tf32(v.w);
        }
        for (int i = t; i < 1024; i += 256) {
            int k = i >> 5, n4 = (i & 31) * 4;
            float4 v = *(const float4*)&W[(size_t)(kc + k) * D_HID + n4];
            uint32_t* p = &Bs[k * BS1_STRIDE + n4];
            p[0] = f2tf32(v.x); p[1] = f2tf32(v.y); p[2] = f2tf32(v.z); p[3] = f2tf32(v.w);
        }
        __syncthreads();

#pragma unroll
        for (int ks = 0; ks < 4; ks++) {
            const int kb = ks * 8;
            uint32_t a[4][4], b[4][2];
            const int ar = wm * 64 + (lane >> 2);
            const int ac = kb + (lane & 3);
#pragma unroll
            for (int mt = 0; mt < 4; mt++) {
                a[mt][0] = As[(ar + mt * 16)     * AS_STRIDE + ac];
                a[mt][1] = As[(ar + mt * 16 + 8) * AS_STRIDE + ac];
                a[mt][2] = As[(ar + mt * 16)     * AS_STRIDE + ac + 4];
                a[mt][3] = As[(ar + mt * 16 + 8) * AS_STRIDE + ac + 4];
            }
            const int bn = wn * 32 + (lane >> 2);
            const int bk = kb + (lane & 3);
#pragma unroll
            for (int nt = 0; nt < 4; nt++) {
                b[nt][0] = Bs[bk       * BS1_STRIDE + bn + nt * 8];
                b[nt][1] = Bs[(bk + 4) * BS1_STRIDE + bn + nt * 8];
            }
#pragma unroll
            for (int mt = 0; mt < 4; mt++)
#pragma unroll
                for (int nt = 0; nt < 4; nt++) mma_tf32(acc[mt][nt], a[mt], b[nt]);
        }
        __syncthreads();
    }

    // epilogue: scale by dinv[row], convert to half2, store
    const int rbase = m0 + wm * 64 + (lane >> 2);
    const int cbase = wn * 32 + (lane & 3) * 2;
#pragma unroll
    for (int mt = 0; mt < 4; mt++) {
#pragma unroll
        for (int half = 0; half < 2; half++) {
            int row = rbase + mt * 16 + half * 8;
            if (row < n) {
                float dv = g_dinv[row];
#pragma unroll
                for (int nt = 0; nt < 4; nt++) {
                    int col = cbase + nt * 8;
                    *(__half2*)&g_g1h[(size_t)row * D_HID + col] =
                        __float22half2_rn(make_float2(dv * acc[mt][nt][2 * half],
                                                      dv * acc[mt][nt][2 * half + 1]));
                }
            }
        }
    }
}

// ---------------- aggregation layer 1: acc1[i] = g1[i] + sum g1[src] (fp16 gather, fp32 acc) ----------------
// one warp per node; lane owns 4 halfs (8B) of the 128-col row.
__global__ void k_agg1(int n) {
    int w = (blockIdx.x * blockDim.x + threadIdx.x) >> 5;
    int lane = threadIdx.x & 31;
    if (w >= n) return;
    const uint2* base = (const uint2*)g_g1h;   // 8B = 4 halfs; row = 32 uint2
    uint2 raw = base[(size_t)w * 32 + lane];
    float2 f0 = __half22float2(*(__half2*)&raw.x);
    float2 f1 = __half22float2(*(__half2*)&raw.y);
    float4 a = make_float4(f0.x, f0.y, f1.x, f1.y);
    int beg = g_rowstart[w], end = g_rowstart[w + 1];
    for (int j = beg; j < end; j++) {
        int s = g_srcidx[j];
        uint2 r = base[(size_t)s * 32 + lane];
        float2 v0 = __half22float2(*(__half2*)&r.x);
        float2 v1 = __half22float2(*(__half2*)&r.y);
        a.x += v0.x; a.y += v0.y; a.z += v1.x; a.w += v1.y;
    }
    ((float4*)g_acc1)[(size_t)w * 32 + lane] = a;
}

// ---------------- GEMM layer 2 (tf32 MMA): h = relu(dinv*acc1 + b1); g2h = fp16(dinv*(h @ W2)) ----------------
#define BS2_STRIDE 68

__global__ void k_gemm2(const float* __restrict__ W, const float* __restrict__ b1, int n) {
    __shared__ uint32_t As[128 * AS_STRIDE];
    __shared__ uint32_t Bs[32 * BS2_STRIDE];

    const int t = threadIdx.x;
    const int wid = t >> 5, lane = t & 31;
    const int wm = wid & 1, wn = wid >> 1;
    const int m0 = blockIdx.x * 128;

    float acc[4][2][4];
#pragma unroll
    for (int mt = 0; mt < 4; mt++)
#pragma unroll
        for (int nt = 0; nt < 2; nt++)
#pragma unroll
            for (int r = 0; r < 4; r++) acc[mt][nt][r] = 0.0f;

    for (int kc = 0; kc < 128; kc += 32) {
        for (int i = t; i < 1024; i += 256) {
            int m = i >> 3, k4 = (i & 7) * 4;
            int row = m0 + m;
            float4 v = make_float4(0.f, 0.f, 0.f, 0.f);
            if (row < n) {
                float dv = g_dinv[row];
                float4 a4 = *(const float4*)&g_acc1[(size_t)row * D_HID + kc + k4];
                float4 bb = *(const float4*)&b1[kc + k4];
                v = make_float4(fmaxf(fmaf(dv, a4.x, bb.x), 0.f),
                                fmaxf(fmaf(dv, a4.y, bb.y), 0.f),
                                fmaxf(fmaf(dv, a4.z, bb.z), 0.f),
                                fmaxf(fmaf(dv, a4.w, bb.w), 0.f));
            }
            uint32_t* p = &As[m * AS_STRIDE + k4];
            p[0] = f2tf32(v.x); p[1] = f2tf32(v.y); p[2] = f2tf32(v.z); p[3] = f2tf32(v.w);
        }
        for (int i = t; i < 512; i += 256) {
            int k = i >> 4, n4 = (i & 15) * 4;
            float4 v = *(const float4*)&W[(size_t)(kc + k) * D_OUT + n4];
            uint32_t* p = &Bs[k * BS2_STRIDE + n4];
            p[0] = f2tf32(v.x); p[1] = f2tf32(v.y); p[2] = f2tf32(v.z); p[3] = f2tf32(v.w);
        }
        __syncthreads();

#pragma unroll
        for (int ks = 0; ks < 4; ks++) {
            const int kb = ks * 8;
            uint32_t a[4][4], b[2][2];
            const int ar = wm * 64 + (lane >> 2);
            const int ac = kb + (lane & 3);
#pragma unroll
            for (int mt = 0; mt < 4; mt++) {
                a[mt][0] = As[(ar + mt * 16)     * AS_STRIDE + ac];
                a[mt][1] = As[(ar + mt * 16 + 8) * AS_STRIDE + ac];
                a[mt][2] = As[(ar + mt * 16)     * AS_STRIDE + ac + 4];
                a[mt][3] = As[(ar + mt * 16 + 8) * AS_STRIDE + ac + 4];
            }
            const int bn = wn * 16 + (lane >> 2);
            const int bk = kb + (lane & 3);
#pragma unroll
            for (int nt = 0; nt < 2; nt++) {
                b[nt][0] = Bs[bk       * BS2_STRIDE + bn + nt * 8];
                b[nt][1] = Bs[(bk + 4) * BS2_STRIDE + bn + nt * 8];
            }
#pragma unroll
            for (int mt = 0; mt < 4; mt++)
#pragma unroll
                for (int nt = 0; nt < 2; nt++) mma_tf32(acc[mt][nt], a[mt], b[nt]);
        }
        __syncthreads();
    }

    const int rbase = m0 + wm * 64 + (lane >> 2);
    const int cbase = wn * 16 + (lane & 3) * 2;
#pragma unroll
    for (int mt = 0; mt < 4; mt++) {
#pragma unroll
        for (int half = 0; half < 2; half++) {
            int row = rbase + mt * 16 + half * 8;
            if (row < n) {
                float dv = g_dinv[row];
#pragma unroll
                for (int nt = 0; nt < 2; nt++) {
                    int col = cbase + nt * 8;
                    *(__half2*)&g_g2h[(size_t)row * D_OUT + col] =
                        __float22half2_rn(make_float2(dv * acc[mt][nt][2 * half],
                                                      dv * acc[mt][nt][2 * half + 1]));
                }
            }
        }
    }
}

// ---------------- aggregation layer 2 + epilogue: out = dinv*(g2[i] + sum g2[src]) + b2 ----------------
// half-warp per node; lane16 owns 4 halfs (8B) of the 64-col row.
__global__ void k_agg2(const float* __restrict__ b2, float* __restrict__ out, int n) {
    int hw = (blockIdx.x * blockDim.x + threadIdx.x) >> 4;
    int lane16 = threadIdx.x & 15;
    if (hw >= n) return;
    const uint2* base = (const uint2*)g_g2h;   // row = 16 uint2
    uint2 raw = base[(size_t)hw * 16 + lane16];
    float2 f0 = __half22float2(*(__half2*)&raw.x);
    float2 f1 = __half22float2(*(__half2*)&raw.y);
    float4 a = make_float4(f0.x, f0.y, f1.x, f1.y);
    int beg = g_rowstart[hw], end = g_rowstart[hw + 1];
    for (int j = beg; j < end; j++) {
        int s = g_srcidx[j];
        uint2 r = base[(size_t)s * 16 + lane16];
        float2 v0 = __half22float2(*(__half2*)&r.x);
        float2 v1 = __half22float2(*(__half2*)&r.y);
        a.x += v0.x; a.y += v0.y; a.z += v1.x; a.w += v1.y;
    }
    float dv = g_dinv[hw];
    float4 b = ((const float4*)b2)[lane16];
    ((float4*)out)[(size_t)hw * 16 + lane16] =
        make_float4(fmaf(dv, a.x, b.x), fmaf(dv, a.y, b.y),
                    fmaf(dv, a.z, b.z), fmaf(dv, a.w, b.w));
}

// ---------------- launch ----------------
extern "C" void kernel_launch(void* const* d_in, const int* in_sizes, int n_in,
                              void* d_out, int out_size) {
    const float* x  = nullptr;
    const void*  ei = nullptr;
    const float* W1 = nullptr;
    const float* b1 = nullptr;
    const float* W2 = nullptr;
    const float* b2 = nullptr;
    int x_elems = 0, ei_elems = 0;

    int imax = 0, imax2 = -1;
    for (int i = 1; i < n_in; i++) if (in_sizes[i] > in_sizes[imax]) imax = i;
    for (int i = 0; i < n_in; i++) {
        if (i == imax) continue;
        if (imax2 < 0 || in_sizes[i] > in_sizes[imax2]) imax2 = i;
    }
    x  = (const float*)d_in[imax];  x_elems  = in_sizes[imax];
    ei = (const void*)d_in[imax2];  ei_elems = in_sizes[imax2];

    for (int i = 0; i < n_in; i++) {
        if (i == imax || i == imax2) continue;
        int s = in_sizes[i];
        if      (s == D_IN * D_HID)  W1 = (const float*)d_in[i];
        else if (s == D_HID)         b1 = (const float*)d_in[i];
        else if (s == D_HID * D_OUT) W2 = (const float*)d_in[i];
        else if (s == D_OUT)         b2 = (const float*)d_in[i];
    }

    float* out = (float*)d_out;
    const int n = x_elems / D_IN;
    const long long E = (long long)ei_elems / 2;
    const int n1 = n + 1;
    const int nb = (n1 + SCAN_BLK - 1) / SCAN_BLK;

    // dtype detection, then CSR build
    k_detect<<<1, 256>>>((const int*)ei, (long long)ei_elems);
    k_zero <<<(n + 255) / 256, 256>>>(n);
    k_count<<<(int)((E + 255) / 256), 256>>>(ei, E, n);
    k_scan1<<<nb, SCAN_BLK>>>(n1);
    k_scan2<<<1, SCAN_BLK>>>(nb);
    k_scan3<<<(n1 + 255) / 256, 256>>>(n);
    k_fill <<<(int)((E + 255) / 256), 256>>>(ei, E, n);

    // layer 1
    k_gemm1<<<(n + 127) / 128, 256>>>(x, W1, n);
    k_agg1 <<<(n + 7) / 8, 256>>>(n);             // 1 node/warp

    // layer 2
    k_gemm2<<<(n + 127) / 128, 256>>>(W2, b1, n);
    k_agg2 <<<(n + 15) / 16, 256>>>(b2, out, n);  // 1 node/half-warp
}

// round 12
// speedup vs baseline: 1.4992x; 1.0377x over previous
#include <cuda_runtime.h>
#include <cuda_fp16.h>
#include <cstdint>

// GCN 2-layer, CSR-gather + tf32 tensor-core GEMMs + fp16 gather tensors.
//   dinv[i] = rsqrt(1 + indeg[i])
//   layer:  g = dinv * (h @ W)            (g stored fp16)
//           acc[i] = g[i] + sum_{e: dst(e)=i} g[src(e)]   (fp32 accumulate)
//           h' = act(dinv[i]*acc[i] + b)

#define D_IN  128
#define D_HID 128
#define D_OUT 64
#define NMAX  100000
#define EMAX  1600000
#define SCAN_BLK 1024
#define NBLK_MAX 1024

// ---- scratch ----
__device__ __align__(16) float g_dinv[NMAX];
__device__ int   g_is64;
__device__ int   g_count[NMAX];
__device__ int   g_rowstart[NMAX + 1];
__device__ int   g_cursor[NMAX];
__device__ int   g_blocksum[NBLK_MAX];
__device__ int   g_srcidx[EMAX];
__device__ __align__(16) __half g_g1h[(size_t)NMAX * D_HID];   // fp16 gather tensor L1
__device__ __align__(16) float  g_acc1[(size_t)NMAX * D_HID];  // fp32 node-local
__device__ __align__(16) __half g_g2h[(size_t)NMAX * D_OUT];   // fp16 gather tensor L2

// ---------------- tf32 helpers ----------------
__device__ __forceinline__ uint32_t f2tf32(float f) {
    uint32_t u;
    asm("cvt.rna.tf32.f32 %0, %1;" : "=r"(u) : "f"(f));
    return u;
}

__device__ __forceinline__ void mma_tf32(float* d, const uint32_t* a, const uint32_t* b) {
    asm volatile(
        "mma.sync.aligned.m16n8k8.row.col.f32.tf32.tf32.f32 "
        "{%0,%1,%2,%3},{%4,%5,%6,%7},{%8,%9},{%0,%1,%2,%3};"
        : "+f"(d[0]), "+f"(d[1]), "+f"(d[2]), "+f"(d[3])
        : "r"(a[0]), "r"(a[1]), "r"(a[2]), "r"(a[3]), "r"(b[0]), "r"(b[1]));
}

// fp16x8 accumulate into fp32x8
__device__ __forceinline__ void acc_u4(float* a, uint4 r) {
    float2 t;
    t = __half22float2(*(__half2*)&r.x); a[0] += t.x; a[1] += t.y;
    t = __half22float2(*(__half2*)&r.y); a[2] += t.x; a[3] += t.y;
    t = __half22float2(*(__half2*)&r.z); a[4] += t.x; a[5] += t.y;
    t = __half22float2(*(__half2*)&r.w); a[6] += t.x; a[7] += t.y;
}

// ---------------- zero counts + edge dtype detection (fused) ----------------
// int64 values < 2^31 -> all odd 32-bit words zero; int32 indices -> mostly nonzero.
__global__ void k_zero_detect(const int* __restrict__ w, long long words32, int n) {
    int i = blockIdx.x * blockDim.x + threadIdx.x;
    if (i < n) g_count[i] = 0;
    if (blockIdx.x == 0) {
        __shared__ int nzflag;
        if (threadIdx.x == 0) nzflag = 0;
        __syncthreads();
        long long limit = words32 < 8192 ? words32 : 8192;
        for (long long k = 1 + 2 * (long long)threadIdx.x; k < limit; k += 2 * blockDim.x)
            if (w[k] != 0) nzflag = 1;   // benign race
        __syncthreads();
        if (threadIdx.x == 0) g_is64 = (nzflag == 0) ? 1 : 0;
    }
}

__device__ __forceinline__ void load_edge(const void* ei, long long E, long long e,
                                          int n, int& src, int& dst) {
    int s, d;
    if (g_is64) {
        const long long* p = (const long long*)ei;
        s = (int)p[e]; d = (int)p[E + e];
    } else {
        const int* p = (const int*)ei;
        s = p[e]; d = p[E + e];
    }
    src = min(max(s, 0), n - 1);
    dst = min(max(d, 0), n - 1);
}

// ---------------- CSR build ----------------
__global__ void k_count(const void* __restrict__ ei, long long E, int n) {
    long long e = (long long)blockIdx.x * blockDim.x + threadIdx.x;
    if (e < E) {
        int src, dst;
        load_edge(ei, E, e, n, src, dst);
        atomicAdd(&g_count[dst], 1);
    }
}

__global__ void k_scan1(int n1) {
    __shared__ int sm[SCAN_BLK];
    int gid = blockIdx.x * SCAN_BLK + threadIdx.x;
    int v = (gid < n1 - 1) ? g_count[gid] : 0;
    sm[threadIdx.x] = v;
    __syncthreads();
    for (int off = 1; off < SCAN_BLK; off <<= 1) {
        int t = (threadIdx.x >= off) ? sm[threadIdx.x - off] : 0;
        __syncthreads();
        sm[threadIdx.x] += t;
        __syncthreads();
    }
    if (gid < n1) g_rowstart[gid] = sm[threadIdx.x] - v;   // exclusive
    if (threadIdx.x == SCAN_BLK - 1) g_blocksum[blockIdx.x] = sm[threadIdx.x];
}

__global__ void k_scan2(int nb) {
    __shared__ int sm[SCAN_BLK];
    int v = (threadIdx.x < nb) ? g_blocksum[threadIdx.x] : 0;
    sm[threadIdx.x] = v;
    __syncthreads();
    for (int off = 1; off < SCAN_BLK; off <<= 1) {
        int t = (threadIdx.x >= off) ? sm[threadIdx.x - off] : 0;
        __syncthreads();
        sm[threadIdx.x] += t;
        __syncthreads();
    }
    if (threadIdx.x < nb) g_blocksum[threadIdx.x] = sm[threadIdx.x] - v;  // exclusive
}

__global__ void k_scan3(int n) {
    int gid = blockIdx.x * blockDim.x + threadIdx.x;
    if (gid <= n) {
        int r = g_rowstart[gid] + g_blocksum[gid / SCAN_BLK];
        g_rowstart[gid] = r;
        if (gid < n) {
            g_cursor[gid] = r;
            g_dinv[gid] = rsqrtf((float)g_count[gid] + 1.0f);  // +1 self-loop
        }
    }
}

__global__ void k_fill(const void* __restrict__ ei, long long E, int n) {
    long long e = (long long)blockIdx.x * blockDim.x + threadIdx.x;
    if (e < E) {
        int src, dst;
        load_edge(ei, E, e, n, src, dst);
        int pos = atomicAdd(&g_cursor[dst], 1);
        pos = min(max(pos, 0), EMAX - 1);
        g_srcidx[pos] = src;
    }
}

// ---------------- GEMM layer 1 (tf32 MMA): g1h = fp16(dinv * (x @ W1)) ----------------
#define AS_STRIDE 36
#define BS1_STRIDE 132

__global__ void k_gemm1(const float* __restrict__ x, const float* __restrict__ W, int n) {
    __shared__ uint32_t As[128 * AS_STRIDE];
    __shared__ uint32_t Bs[32 * BS1_STRIDE];

    const int t = threadIdx.x;
    const int wid = t >> 5, lane = t & 31;
    const int wm = wid & 1, wn = wid >> 1;
    const int m0 = blockIdx.x * 128;

    float acc[4][4][4];
#pragma unroll
    for (int mt = 0; mt < 4; mt++)
#pragma unroll
        for (int nt = 0; nt < 4; nt++)
#pragma unroll
            for (int r = 0; r < 4; r++) acc[mt][nt][r] = 0.0f;

    for (int kc = 0; kc < 128; kc += 32) {
        for (int i = t; i < 1024; i += 256) {
            int m = i >> 3, k4 = (i & 7) * 4;
            int row = m0 + m;
            float4 v = make_float4(0.f, 0.f, 0.f, 0.f);
            if (row < n) v = *(const float4*)&x[(size_t)row * D_IN + kc + k4];
            uint32_t* p = &As[m * AS_STRIDE + k4];
            p[0] = f2tf32(v.x); p[1] = f2tf32(v.y); p[2] = f2tf32(v.z); p[3] = f2tf32(v.w);
        }
        for (int i = t; i < 1024; i += 256) {
            int k = i >> 5, n4 = (i & 31) * 4;
            float4 v = *(const float4*)&W[(size_t)(kc + k) * D_HID + n4];
            uint32_t* p = &Bs[k * BS1_STRIDE + n4];
            p[0] = f2tf32(v.x); p[1] = f2tf32(v.y); p[2] = f2tf32(v.z); p[3] = f2tf32(v.w);
        }
        __syncthreads();

#pragma unroll
        for (int ks = 0; ks < 4; ks++) {
            const int kb = ks * 8;
            uint32_t a[4][4], b[4][2];
            const int ar = wm * 64 + (lane >> 2);
            const int ac = kb + (lane & 3);
#pragma unroll
            for (int mt = 0; mt < 4; mt++) {
                a[mt][0] = As[(ar + mt * 16)     * AS_STRIDE + ac];
                a[mt][1] = As[(ar + mt * 16 + 8) * AS_STRIDE + ac];
                a[mt][2] = As[(ar + mt * 16)     * AS_STRIDE + ac + 4];
                a[mt][3] = As[(ar + mt * 16 + 8) * AS_STRIDE + ac + 4];
            }
            const int bn = wn * 32 + (lane >> 2);
            const int bk = kb + (lane & 3);
#pragma unroll
            for (int nt = 0; nt < 4; nt++) {
                b[nt][0] = Bs[bk       * BS1_STRIDE + bn + nt * 8];
                b[nt][1] = Bs[(bk + 4) * BS1_STRIDE + bn + nt * 8];
            }
#pragma unroll
            for (int mt = 0; mt < 4; mt++)
#pragma unroll
                for (int nt = 0; nt < 4; nt++) mma_tf32(acc[mt][nt], a[mt], b[nt]);
        }
        __syncthreads();
    }

    const int rbase = m0 + wm * 64 + (lane >> 2);
    const int cbase = wn * 32 + (lane & 3) * 2;
#pragma unroll
    for (int mt = 0; mt < 4; mt++) {
#pragma unroll
        for (int half = 0; half < 2; half++) {
            int row = rbase + mt * 16 + half * 8;
            if (row < n) {
                float dv = g_dinv[row];
#pragma unroll
                for (int nt = 0; nt < 4; nt++) {
                    int col = cbase + nt * 8;
                    *(__half2*)&g_g1h[(size_t)row * D_HID + col] =
                        __float22half2_rn(make_float2(dv * acc[mt][nt][2 * half],
                                                      dv * acc[mt][nt][2 * half + 1]));
                }
            }
        }
    }
}

// ---------------- aggregation layer 1 ----------------
// 2 nodes/warp; 16 lanes/node; lane owns uint4 (8 halfs, 16B) of 256B row.
// Edge loop unrolled x4 with batched srcidx prefetch (MLP=4).
__global__ void k_agg1(int n) {
    int gw = (blockIdx.x * blockDim.x + threadIdx.x) >> 5;
    int lane = threadIdx.x & 31;
    int node = gw * 2 + (lane >> 4);
    int lane16 = lane & 15;
    if (node >= n) return;

    const uint4* base = (const uint4*)g_g1h;   // row = 16 uint4
    float a[8];
    {
        uint4 r = base[(size_t)node * 16 + lane16];
        float2 t;
        t = __half22float2(*(__half2*)&r.x); a[0] = t.x; a[1] = t.y;
        t = __half22float2(*(__half2*)&r.y); a[2] = t.x; a[3] = t.y;
        t = __half22float2(*(__half2*)&r.z); a[4] = t.x; a[5] = t.y;
        t = __half22float2(*(__half2*)&r.w); a[6] = t.x; a[7] = t.y;
    }

    int beg = g_rowstart[node], end = g_rowstart[node + 1];
    int j = beg;
    for (; j + 4 <= end; j += 4) {
        int s0 = g_srcidx[j], s1 = g_srcidx[j + 1], s2 = g_srcidx[j + 2], s3 = g_srcidx[j + 3];
        uint4 r0 = base[(size_t)s0 * 16 + lane16];
        uint4 r1 = base[(size_t)s1 * 16 + lane16];
        uint4 r2 = base[(size_t)s2 * 16 + lane16];
        uint4 r3 = base[(size_t)s3 * 16 + lane16];
        acc_u4(a, r0); acc_u4(a, r1); acc_u4(a, r2); acc_u4(a, r3);
    }
    for (; j < end; j++) {
        uint4 r = base[(size_t)g_srcidx[j] * 16 + lane16];
        acc_u4(a, r);
    }

    float4* outp = (float4*)g_acc1 + (size_t)node * 32 + lane16 * 2;
    outp[0] = make_float4(a[0], a[1], a[2], a[3]);
    outp[1] = make_float4(a[4], a[5], a[6], a[7]);
}

// ---------------- GEMM layer 2 (tf32 MMA): h = relu(dinv*acc1 + b1); g2h = fp16(dinv*(h @ W2)) ----------------
#define BS2_STRIDE 68

__global__ void k_gemm2(const float* __restrict__ W, const float* __restrict__ b1, int n) {
    __shared__ uint32_t As[128 * AS_STRIDE];
    __shared__ uint32_t Bs[32 * BS2_STRIDE];

    const int t = threadIdx.x;
    const int wid = t >> 5, lane = t & 31;
    const int wm = wid & 1, wn = wid >> 1;
    const int m0 = blockIdx.x * 128;

    float acc[4][2][4];
#pragma unroll
    for (int mt = 0; mt < 4; mt++)
#pragma unroll
        for (int nt = 0; nt < 2; nt++)
#pragma unroll
            for (int r = 0; r < 4; r++) acc[mt][nt][r] = 0.0f;

    for (int kc = 0; kc < 128; kc += 32) {
        for (int i = t; i < 1024; i += 256) {
            int m = i >> 3, k4 = (i & 7) * 4;
            int row = m0 + m;
            float4 v = make_float4(0.f, 0.f, 0.f, 0.f);
            if (row < n) {
                float dv = g_dinv[row];
                float4 a4 = *(const float4*)&g_acc1[(size_t)row * D_HID + kc + k4];
                float4 bb = *(const float4*)&b1[kc + k4];
                v = make_float4(fmaxf(fmaf(dv, a4.x, bb.x), 0.f),
                                fmaxf(fmaf(dv, a4.y, bb.y), 0.f),
                                fmaxf(fmaf(dv, a4.z, bb.z), 0.f),
                                fmaxf(fmaf(dv, a4.w, bb.w), 0.f));
            }
            uint32_t* p = &As[m * AS_STRIDE + k4];
            p[0] = f2tf32(v.x); p[1] = f2tf32(v.y); p[2] = f2tf32(v.z); p[3] = f2tf32(v.w);
        }
        for (int i = t; i < 512; i += 256) {
            int k = i >> 4, n4 = (i & 15) * 4;
            float4 v = *(const float4*)&W[(size_t)(kc + k) * D_OUT + n4];
            uint32_t* p = &Bs[k * BS2_STRIDE + n4];
            p[0] = f2tf32(v.x); p[1] = f2tf32(v.y); p[2] = f2tf32(v.z); p[3] = f2tf32(v.w);
        }
        __syncthreads();

#pragma unroll
        for (int ks = 0; ks < 4; ks++) {
            const int kb = ks * 8;
            uint32_t a[4][4], b[2][2];
            const int ar = wm * 64 + (lane >> 2);
            const int ac = kb + (lane & 3);
#pragma unroll
            for (int mt = 0; mt < 4; mt++) {
                a[mt][0] = As[(ar + mt * 16)     * AS_STRIDE + ac];
                a[mt][1] = As[(ar + mt * 16 + 8) * AS_STRIDE + ac];
                a[mt][2] = As[(ar + mt * 16)     * AS_STRIDE + ac + 4];
                a[mt][3] = As[(ar + mt * 16 + 8) * AS_STRIDE + ac + 4];
            }
            const int bn = wn * 16 + (lane >> 2);
            const int bk = kb + (lane & 3);
#pragma unroll
            for (int nt = 0; nt < 2; nt++) {
                b[nt][0] = Bs[bk       * BS2_STRIDE + bn + nt * 8];
                b[nt][1] = Bs[(bk + 4) * BS2_STRIDE + bn + nt * 8];
            }
#pragma unroll
            for (int mt = 0; mt < 4; mt++)
#pragma unroll
                for (int nt = 0; nt < 2; nt++) mma_tf32(acc[mt][nt], a[mt], b[nt]);
        }
        __syncthreads();
    }

    const int rbase = m0 + wm * 64 + (lane >> 2);
    const int cbase = wn * 16 + (lane & 3) * 2;
#pragma unroll
    for (int mt = 0; mt < 4; mt++) {
#pragma unroll
        for (int half = 0; half < 2; half++) {
            int row = rbase + mt * 16 + half * 8;
            if (row < n) {
                float dv = g_dinv[row];
#pragma unroll
                for (int nt = 0; nt < 2; nt++) {
                    int col = cbase + nt * 8;
                    *(__half2*)&g_g2h[(size_t)row * D_OUT + col] =
                        __float22half2_rn(make_float2(dv * acc[mt][nt][2 * half],
                                                      dv * acc[mt][nt][2 * half + 1]));
                }
            }
        }
    }
}

// ---------------- aggregation layer 2 + epilogue ----------------
// 4 nodes/warp; 8 lanes/node; lane owns uint4 (8 halfs, 16B) of 128B row.
__global__ void k_agg2(const float* __restrict__ b2, float* __restrict__ out, int n) {
    int gw = (blockIdx.x * blockDim.x + threadIdx.x) >> 5;
    int lane = threadIdx.x & 31;
    int node = gw * 4 + (lane >> 3);
    int lane8 = lane & 7;
    if (node >= n) return;

    const uint4* base = (const uint4*)g_g2h;   // row = 8 uint4
    float a[8];
    {
        uint4 r = base[(size_t)node * 8 + lane8];
        float2 t;
        t = __half22float2(*(__half2*)&r.x); a[0] = t.x; a[1] = t.y;
        t = __half22float2(*(__half2*)&r.y); a[2] = t.x; a[3] = t.y;
        t = __half22float2(*(__half2*)&r.z); a[4] = t.x; a[5] = t.y;
        t = __half22float2(*(__half2*)&r.w); a[6] = t.x; a[7] = t.y;
    }

    int beg = g_rowstart[node], end = g_rowstart[node + 1];
    int j = beg;
    for (; j + 4 <= end; j += 4) {
        int s0 = g_srcidx[j], s1 = g_srcidx[j + 1], s2 = g_srcidx[j + 2], s3 = g_srcidx[j + 3];
        uint4 r0 = base[(size_t)s0 * 8 + lane8];
        uint4 r1 = base[(size_t)s1 * 8 + lane8];
        uint4 r2 = base[(size_t)s2 * 8 + lane8];
        uint4 r3 = base[(size_t)s3 * 8 + lane8];
        acc_u4(a, r0); acc_u4(a, r1); acc_u4(a, r2); acc_u4(a, r3);
    }
    for (; j < end; j++) {
        uint4 r = base[(size_t)g_srcidx[j] * 8 + lane8];
        acc_u4(a, r);
    }

    float dv = g_dinv[node];
    const float4* b24 = (const float4*)b2;
    float4 bb0 = b24[lane8 * 2], bb1 = b24[lane8 * 2 + 1];
    float4* outp = (float4*)out + (size_t)node * 16 + lane8 * 2;
    outp[0] = make_float4(fmaf(dv, a[0], bb0.x), fmaf(dv, a[1], bb0.y),
                          fmaf(dv, a[2], bb0.z), fmaf(dv, a[3], bb0.w));
    outp[1] = make_float4(fmaf(dv, a[4], bb1.x), fmaf(dv, a[5], bb1.y),
                          fmaf(dv, a[6], bb1.z), fmaf(dv, a[7], bb1.w));
}

// ---------------- launch ----------------
extern "C" void kernel_launch(void* const* d_in, const int* in_sizes, int n_in,
                              void* d_out, int out_size) {
    const float* x  = nullptr;
    const void*  ei = nullptr;
    const float* W1 = nullptr;
    const float* b1 = nullptr;
    const float* W2 = nullptr;
    const float* b2 = nullptr;
    int x_elems = 0, ei_elems = 0;

    int imax = 0, imax2 = -1;
    for (int i = 1; i < n_in; i++) if (in_sizes[i] > in_sizes[imax]) imax = i;
    for (int i = 0; i < n_in; i++) {
        if (i == imax) continue;
        if (imax2 < 0 || in_sizes[i] > in_sizes[imax2]) imax2 = i;
    }
    x  = (const float*)d_in[imax];  x_elems  = in_sizes[imax];
    ei = (const void*)d_in[imax2];  ei_elems = in_sizes[imax2];

    for (int i = 0; i < n_in; i++) {
        if (i == imax || i == imax2) continue;
        int s = in_sizes[i];
        if      (s == D_IN * D_HID)  W1 = (const float*)d_in[i];
        else if (s == D_HID)         b1 = (const float*)d_in[i];
        else if (s == D_HID * D_OUT) W2 = (const float*)d_in[i];
        else if (s == D_OUT)         b2 = (const float*)d_in[i];
    }

    float* out = (float*)d_out;
    const int n = x_elems / D_IN;
    const long long E = (long long)ei_elems / 2;
    const int n1 = n + 1;
    const int nb = (n1 + SCAN_BLK - 1) / SCAN_BLK;

    // CSR build (detect fused into zero)
    k_zero_detect<<<(n + 255) / 256, 256>>>((const int*)ei, (long long)ei_elems, n);
    k_count<<<(int)((E + 255) / 256), 256>>>(ei, E, n);
    k_scan1<<<nb, SCAN_BLK>>>(n1);
    k_scan2<<<1, SCAN_BLK>>>(nb);
    k_scan3<<<(n1 + 255) / 256, 256>>>(n);
    k_fill <<<(int)((E + 255) / 256), 256>>>(ei, E, n);

    // layer 1
    k_gemm1<<<(n + 127) / 128, 256>>>(x, W1, n);
    k_agg1 <<<(n + 15) / 16, 256>>>(n);            // 2 nodes/warp, 16/block

    // layer 2
    k_gemm2<<<(n + 127) / 128, 256>>>(W2, b1, n);
    k_agg2 <<<(n + 31) / 32, 256>>>(b2, out, n);   // 4 nodes/warp, 32/block
}

// round 13
// speedup vs baseline: 1.5601x; 1.0406x over previous
#include <cuda_runtime.h>
#include <cuda_fp16.h>
#include <cstdint>

// GCN 2-layer, CSR-gather + tf32 tensor-core GEMMs + fp16 gather tensors.
//   dinv[i] = rsqrt(1 + indeg[i])
//   L1: g1 = dinv*(x@W1) [fp16];  h = relu(dinv*(g1[i]+sum g1[src]) + b1) [fp16, fused into agg1]
//   L2: g2 = dinv*(h@W2) [fp16];  out = dinv*(g2[i]+sum g2[src]) + b2
// CSR built with: count -> single-kernel decoupled-lookback scan -> fill.

#define D_IN  128
#define D_HID 128
#define D_OUT 64
#define NMAX  100000
#define EMAX  1600000
#define SCAN_BLK 1024
#define NBLK_MAX 128

// ---- scratch ----
__device__ __align__(16) float g_dinv[NMAX];
__device__ int   g_is64;
__device__ int   g_count[NMAX];
__device__ int   g_rowstart[NMAX + 1];
__device__ int   g_cursor[NMAX];
__device__ volatile unsigned long long g_blkpack[NBLK_MAX];  // (aggregate<<32)|1
__device__ int   g_srcidx[EMAX];
__device__ __align__(16) __half g_g1h[(size_t)NMAX * D_HID];  // fp16 gather tensor L1
__device__ __align__(16) __half g_h1h[(size_t)NMAX * D_HID];  // fp16 hidden activations
__device__ __align__(16) __half g_g2h[(size_t)NMAX * D_OUT];  // fp16 gather tensor L2

// ---------------- tf32 helpers ----------------
__device__ __forceinline__ uint32_t f2tf32(float f) {
    uint32_t u;
    asm("cvt.rna.tf32.f32 %0, %1;" : "=r"(u) : "f"(f));
    return u;
}

__device__ __forceinline__ void mma_tf32(float* d, const uint32_t* a, const uint32_t* b) {
    asm volatile(
        "mma.sync.aligned.m16n8k8.row.col.f32.tf32.tf32.f32 "
        "{%0,%1,%2,%3},{%4,%5,%6,%7},{%8,%9},{%0,%1,%2,%3};"
        : "+f"(d[0]), "+f"(d[1]), "+f"(d[2]), "+f"(d[3])
        : "r"(a[0]), "r"(a[1]), "r"(a[2]), "r"(a[3]), "r"(b[0]), "r"(b[1]));
}

// fp16x8 accumulate into fp32x8
__device__ __forceinline__ void acc_u4(float* a, uint4 r) {
    float2 t;
    t = __half22float2(*(__half2*)&r.x); a[0] += t.x; a[1] += t.y;
    t = __half22float2(*(__half2*)&r.y); a[2] += t.x; a[3] += t.y;
    t = __half22float2(*(__half2*)&r.z); a[4] += t.x; a[5] += t.y;
    t = __half22float2(*(__half2*)&r.w); a[6] += t.x; a[7] += t.y;
}

// ---------------- zero counts/flags + edge dtype detection (fused) ----------------
__global__ void k_zero_detect(const int* __restrict__ w, long long words32, int n) {
    int i = blockIdx.x * blockDim.x + threadIdx.x;
    if (i < n) g_count[i] = 0;
    if (i < NBLK_MAX) g_blkpack[i] = 0ull;
    if (blockIdx.x == 0) {
        __shared__ int nzflag;
        if (threadIdx.x == 0) nzflag = 0;
        __syncthreads();
        long long limit = words32 < 8192 ? words32 : 8192;
        for (long long k = 1 + 2 * (long long)threadIdx.x; k < limit; k += 2 * blockDim.x)
            if (w[k] != 0) nzflag = 1;   // benign race
        __syncthreads();
        if (threadIdx.x == 0) g_is64 = (nzflag == 0) ? 1 : 0;
    }
}

// ---------------- CSR build: count (4 edges/thread, vectorized) ----------------
__global__ void k_count(const void* __restrict__ ei, long long E, int n) {
    long long q = (long long)blockIdx.x * blockDim.x + threadIdx.x;  // quad index
    long long e0 = q * 4;
    if (e0 >= E) return;
    int d[4];
    int cnt = (int)((E - e0) < 4 ? (E - e0) : 4);
    if (g_is64) {
        const longlong2* p = (const longlong2*)((const long long*)ei + E + e0);
        if (cnt == 4) {
            longlong2 a = p[0], b = p[1];
            d[0] = (int)a.x; d[1] = (int)a.y; d[2] = (int)b.x; d[3] = (int)b.y;
        } else {
            const long long* s = (const long long*)ei + E + e0;
            for (int k = 0; k < cnt; k++) d[k] = (int)s[k];
        }
    } else {
        if (cnt == 4) {
            int4 a = *(const int4*)((const int*)ei + E + e0);
            d[0] = a.x; d[1] = a.y; d[2] = a.z; d[3] = a.w;
        } else {
            const int* s = (const int*)ei + E + e0;
            for (int k = 0; k < cnt; k++) d[k] = s[k];
        }
    }
    for (int k = 0; k < cnt; k++) {
        int dst = min(max(d[k], 0), n - 1);
        atomicAdd(&g_count[dst], 1);
    }
}

// ---------------- single-kernel scan: decoupled lookback ----------------
// exclusive scan of count[0..n-1] (entry n treated as 0) -> rowstart[0..n];
// also writes cursor and dinv.
__global__ void k_scan(int n) {
    __shared__ int sm[SCAN_BLK];
    __shared__ int s_prev;
    const int b = blockIdx.x;
    const int tid = threadIdx.x;
    const int gid = b * SCAN_BLK + tid;
    const int n1 = n + 1;

    int v = (gid < n) ? g_count[gid] : 0;
    sm[tid] = v;
    __syncthreads();
    for (int off = 1; off < SCAN_BLK; off <<= 1) {
        int t = (tid >= off) ? sm[tid - off] : 0;
        __syncthreads();
        sm[tid] += t;
        __syncthreads();
    }
    int incl = sm[tid];

    // publish this block's aggregate (packed with ready-bit)
    if (tid == SCAN_BLK - 1) {
        unsigned long long pack = ((unsigned long long)(unsigned)incl << 32) | 1ull;
        g_blkpack[b] = pack;
    }

    // lookback: sum all predecessor aggregates (blocks only wait on lower IDs)
    if (tid == 0) s_prev = 0;
    __syncthreads();
    int part = 0;
    for (int j = tid; j < b; j += SCAN_BLK) {
        unsigned long long w;
        do { w = g_blkpack[j]; } while (w == 0ull);
        part += (int)(w >> 32);
    }
    if (part) atomicAdd(&s_prev, part);
    __syncthreads();
    int prev = s_prev;

    int excl = prev + incl - v;
    if (gid < n1) g_rowstart[gid] = excl;
    if (gid < n) {
        g_cursor[gid] = excl;
        g_dinv[gid] = rsqrtf((float)v + 1.0f);  // +1 self-loop
    }
}

// ---------------- CSR build: fill (4 edges/thread, vectorized) ----------------
__global__ void k_fill(const void* __restrict__ ei, long long E, int n) {
    long long q = (long long)blockIdx.x * blockDim.x + threadIdx.x;
    long long e0 = q * 4;
    if (e0 >= E) return;
    int s[4], d[4];
    int cnt = (int)((E - e0) < 4 ? (E - e0) : 4);
    if (g_is64) {
        if (cnt == 4) {
            const longlong2* ps = (const longlong2*)((const long long*)ei + e0);
            const longlong2* pd = (const longlong2*)((const long long*)ei + E + e0);
            longlong2 a = ps[0], b = ps[1], c = pd[0], f = pd[1];
            s[0] = (int)a.x; s[1] = (int)a.y; s[2] = (int)b.x; s[3] = (int)b.y;
            d[0] = (int)c.x; d[1] = (int)c.y; d[2] = (int)f.x; d[3] = (int)f.y;
        } else {
            const long long* ps = (const long long*)ei + e0;
            const long long* pd = (const long long*)ei + E + e0;
            for (int k = 0; k < cnt; k++) { s[k] = (int)ps[k]; d[k] = (int)pd[k]; }
        }
    } else {
        if (cnt == 4) {
            int4 a = *(const int4*)((const int*)ei + e0);
            int4 c = *(const int4*)((const int*)ei + E + e0);
            s[0] = a.x; s[1] = a.y; s[2] = a.z; s[3] = a.w;
            d[0] = c.x; d[1] = c.y; d[2] = c.z; d[3] = c.w;
        } else {
            const int* ps = (const int*)ei + e0;
            const int* pd = (const int*)ei + E + e0;
            for (int k = 0; k < cnt; k++) { s[k] = ps[k]; d[k] = pd[k]; }
        }
    }
    for (int k = 0; k < cnt; k++) {
        int src = min(max(s[k], 0), n - 1);
        int dst = min(max(d[k], 0), n - 1);
        int pos = atomicAdd(&g_cursor[dst], 1);
        pos = min(max(pos, 0), EMAX - 1);
        g_srcidx[pos] = src;
    }
}

// ---------------- GEMM layer 1 (tf32 MMA): g1h = fp16(dinv * (x @ W1)) ----------------
#define AS_STRIDE 36
#define BS1_STRIDE 132

__global__ void k_gemm1(const float* __restrict__ x, const float* __restrict__ W, int n) {
    __shared__ uint32_t As[128 * AS_STRIDE];
    __shared__ uint32_t Bs[32 * BS1_STRIDE];

    const int t = threadIdx.x;
    const int wid = t >> 5, lane = t & 31;
    const int wm = wid & 1, wn = wid >> 1;
    const int m0 = blockIdx.x * 128;

    float acc[4][4][4];
#pragma unroll
    for (int mt = 0; mt < 4; mt++)
#pragma unroll
        for (int nt = 0; nt < 4; nt++)
#pragma unroll
            for (int r = 0; r < 4; r++) acc[mt][nt][r] = 0.0f;

    for (int kc = 0; kc < 128; kc += 32) {
        for (int i = t; i < 1024; i += 256) {
            int m = i >> 3, k4 = (i & 7) * 4;
            int row = m0 + m;
            float4 v = make_float4(0.f, 0.f, 0.f, 0.f);
            if (row < n) v = *(const float4*)&x[(size_t)row * D_IN + kc + k4];
            uint32_t* p = &As[m * AS_STRIDE + k4];
            p[0] = f2tf32(v.x); p[1] = f2tf32(v.y); p[2] = f2tf32(v.z); p[3] = f2tf32(v.w);
        }
        for (int i = t; i < 1024; i += 256) {
            int k = i >> 5, n4 = (i & 31) * 4;
            float4 v = *(const float4*)&W[(size_t)(kc + k) * D_HID + n4];
            uint32_t* p = &Bs[k * BS1_STRIDE + n4];
            p[0] = f2tf32(v.x); p[1] = f2tf32(v.y); p[2] = f2tf32(v.z); p[3] = f2tf32(v.w);
        }
        __syncthreads();

#pragma unroll
        for (int ks = 0; ks < 4; ks++) {
            const int kb = ks * 8;
            uint32_t a[4][4], b[4][2];
            const int ar = wm * 64 + (lane >> 2);
            const int ac = kb + (lane & 3);
#pragma unroll
            for (int mt = 0; mt < 4; mt++) {
                a[mt][0] = As[(ar + mt * 16)     * AS_STRIDE + ac];
                a[mt][1] = As[(ar + mt * 16 + 8) * AS_STRIDE + ac];
                a[mt][2] = As[(ar + mt * 16)     * AS_STRIDE + ac + 4];
                a[mt][3] = As[(ar + mt * 16 + 8) * AS_STRIDE + ac + 4];
            }
            const int bn = wn * 32 + (lane >> 2);
            const int bk = kb + (lane & 3);
#pragma unroll
            for (int nt = 0; nt < 4; nt++) {
                b[nt][0] = Bs[bk       * BS1_STRIDE + bn + nt * 8];
                b[nt][1] = Bs[(bk + 4) * BS1_STRIDE + bn + nt * 8];
            }
#pragma unroll
            for (int mt = 0; mt < 4; mt++)
#pragma unroll
                for (int nt = 0; nt < 4; nt++) mma_tf32(acc[mt][nt], a[mt], b[nt]);
        }
        __syncthreads();
    }

    const int rbase = m0 + wm * 64 + (lane >> 2);
    const int cbase = wn * 32 + (lane & 3) * 2;
#pragma unroll
    for (int mt = 0; mt < 4; mt++) {
#pragma unroll
        for (int half = 0; half < 2; half++) {
            int row = rbase + mt * 16 + half * 8;
            if (row < n) {
                float dv = g_dinv[row];
#pragma unroll
                for (int nt = 0; nt < 4; nt++) {
                    int col = cbase + nt * 8;
                    *(__half2*)&g_g1h[(size_t)row * D_HID + col] =
                        __float22half2_rn(make_float2(dv * acc[mt][nt][2 * half],
                                                      dv * acc[mt][nt][2 * half + 1]));
                }
            }
        }
    }
}

// ---------------- aggregation layer 1 + L2 activation (fused) ----------------
// 2 nodes/warp; 16 lanes/node; lane owns uint4 (8 halfs) of 256B row.
// h = relu(dinv*(g1[i]+sum g1[src]) + b1), stored fp16.
__global__ void k_agg1(const float* __restrict__ b1, int n) {
    int gw = (blockIdx.x * blockDim.x + threadIdx.x) >> 5;
    int lane = threadIdx.x & 31;
    int node = gw * 2 + (lane >> 4);
    int lane16 = lane & 15;
    if (node >= n) return;

    const uint4* base = (const uint4*)g_g1h;   // row = 16 uint4
    float a[8];
    {
        uint4 r = base[(size_t)node * 16 + lane16];
        float2 t;
        t = __half22float2(*(__half2*)&r.x); a[0] = t.x; a[1] = t.y;
        t = __half22float2(*(__half2*)&r.y); a[2] = t.x; a[3] = t.y;
        t = __half22float2(*(__half2*)&r.z); a[4] = t.x; a[5] = t.y;
        t = __half22float2(*(__half2*)&r.w); a[6] = t.x; a[7] = t.y;
    }

    int beg = g_rowstart[node], end = g_rowstart[node + 1];
    int j = beg;
    for (; j + 4 <= end; j += 4) {
        int s0 = g_srcidx[j], s1 = g_srcidx[j + 1], s2 = g_srcidx[j + 2], s3 = g_srcidx[j + 3];
        uint4 r0 = base[(size_t)s0 * 16 + lane16];
        uint4 r1 = base[(size_t)s1 * 16 + lane16];
        uint4 r2 = base[(size_t)s2 * 16 + lane16];
        uint4 r3 = base[(size_t)s3 * 16 + lane16];
        acc_u4(a, r0); acc_u4(a, r1); acc_u4(a, r2); acc_u4(a, r3);
    }
    for (; j < end; j++) {
        uint4 r = base[(size_t)g_srcidx[j] * 16 + lane16];
        acc_u4(a, r);
    }

    // fused layer-2 input activation: relu(dinv*a + b1) -> fp16
    float dv = g_dinv[node];
    float4 bb0 = *(const float4*)&b1[lane16 * 8];
    float4 bb1 = *(const float4*)&b1[lane16 * 8 + 4];
    float h0 = fmaxf(fmaf(dv, a[0], bb0.x), 0.f), h1 = fmaxf(fmaf(dv, a[1], bb0.y), 0.f);
    float h2 = fmaxf(fmaf(dv, a[2], bb0.z), 0.f), h3 = fmaxf(fmaf(dv, a[3], bb0.w), 0.f);
    float h4 = fmaxf(fmaf(dv, a[4], bb1.x), 0.f), h5 = fmaxf(fmaf(dv, a[5], bb1.y), 0.f);
    float h6 = fmaxf(fmaf(dv, a[6], bb1.z), 0.f), h7 = fmaxf(fmaf(dv, a[7], bb1.w), 0.f);
    uint4 outw;
    *(__half2*)&outw.x = __float22half2_rn(make_float2(h0, h1));
    *(__half2*)&outw.y = __float22half2_rn(make_float2(h2, h3));
    *(__half2*)&outw.z = __float22half2_rn(make_float2(h4, h5));
    *(__half2*)&outw.w = __float22half2_rn(make_float2(h6, h7));
    ((uint4*)g_h1h)[(size_t)node * 16 + lane16] = outw;
}

// ---------------- GEMM layer 2 (tf32 MMA): g2h = fp16(dinv*(h @ W2)), h fp16 ----------------
#define BS2_STRIDE 68

__global__ void k_gemm2(const float* __restrict__ W, int n) {
    __shared__ uint32_t As[128 * AS_STRIDE];
    __shared__ uint32_t Bs[32 * BS2_STRIDE];

    const int t = threadIdx.x;
    const int wid = t >> 5, lane = t & 31;
    const int wm = wid & 1, wn = wid >> 1;
    const int m0 = blockIdx.x * 128;

    float acc[4][2][4];
#pragma unroll
    for (int mt = 0; mt < 4; mt++)
#pragma unroll
        for (int nt = 0; nt < 2; nt++)
#pragma unroll
            for (int r = 0; r < 4; r++) acc[mt][nt][r] = 0.0f;

    for (int kc = 0; kc < 128; kc += 32) {
        for (int i = t; i < 1024; i += 256) {
            int m = i >> 3, k4 = (i & 7) * 4;
            int row = m0 + m;
            uint32_t* p = &As[m * AS_STRIDE + k4];
            if (row < n) {
                uint2 raw = *(const uint2*)&g_h1h[(size_t)row * D_HID + kc + k4];
                float2 t0 = __half22float2(*(__half2*)&raw.x);
                float2 t1 = __half22float2(*(__half2*)&raw.y);
                p[0] = f2tf32(t0.x); p[1] = f2tf32(t0.y);
                p[2] = f2tf32(t1.x); p[3] = f2tf32(t1.y);
            } else {
                p[0] = 0u; p[1] = 0u; p[2] = 0u; p[3] = 0u;
            }
        }
        for (int i = t; i < 512; i += 256) {
            int k = i >> 4, n4 = (i & 15) * 4;
            float4 v = *(const float4*)&W[(size_t)(kc + k) * D_OUT + n4];
            uint32_t* p = &Bs[k * BS2_STRIDE + n4];
            p[0] = f2tf32(v.x); p[1] = f2tf32(v.y); p[2] = f2tf32(v.z); p[3] = f2tf32(v.w);
        }
        __syncthreads();

#pragma unroll
        for (int ks = 0; ks < 4; ks++) {
            const int kb = ks * 8;
            uint32_t a[4][4], b[2][2];
            const int ar = wm * 64 + (lane >> 2);
            const int ac = kb + (lane & 3);
#pragma unroll
            for (int mt = 0; mt < 4; mt++) {
                a[mt][0] = As[(ar + mt * 16)     * AS_STRIDE + ac];
                a[mt][1] = As[(ar + mt * 16 + 8) * AS_STRIDE + ac];
                a[mt][2] = As[(ar + mt * 16)     * AS_STRIDE + ac + 4];
                a[mt][3] = As[(ar + mt * 16 + 8) * AS_STRIDE + ac + 4];
            }
            const int bn = wn * 16 + (lane >> 2);
            const int bk = kb + (lane & 3);
#pragma unroll
            for (int nt = 0; nt < 2; nt++) {
                b[nt][0] = Bs[bk       * BS2_STRIDE + bn + nt * 8];
                b[nt][1] = Bs[(bk + 4) * BS2_STRIDE + bn + nt * 8];
            }
#pragma unroll
            for (int mt = 0; mt < 4; mt++)
#pragma unroll
                for (int nt = 0; nt < 2; nt++) mma_tf32(acc[mt][nt], a[mt], b[nt]);
        }
        __syncthreads();
    }

    const int rbase = m0 + wm * 64 + (lane >> 2);
    const int cbase = wn * 16 + (lane & 3) * 2;
#pragma unroll
    for (int mt = 0; mt < 4; mt++) {
#pragma unroll
        for (int half = 0; half < 2; half++) {
            int row = rbase + mt * 16 + half * 8;
            if (row < n) {
                float dv = g_dinv[row];
#pragma unroll
                for (int nt = 0; nt < 2; nt++) {
                    int col = cbase + nt * 8;
                    *(__half2*)&g_g2h[(size_t)row * D_OUT + col] =
                        __float22half2_rn(make_float2(dv * acc[mt][nt][2 * half],
                                                      dv * acc[mt][nt][2 * half + 1]));
                }
            }
        }
    }
}

// ---------------- aggregation layer 2 + epilogue ----------------
// 4 nodes/warp; 8 lanes/node; lane owns uint4 (8 halfs) of 128B row.
__global__ void k_agg2(const float* __restrict__ b2, float* __restrict__ out, int n) {
    int gw = (blockIdx.x * blockDim.x + threadIdx.x) >> 5;
    int lane = threadIdx.x & 31;
    int node = gw * 4 + (lane >> 3);
    int lane8 = lane & 7;
    if (node >= n) return;

    const uint4* base = (const uint4*)g_g2h;   // row = 8 uint4
    float a[8];
    {
        uint4 r = base[(size_t)node * 8 + lane8];
        float2 t;
        t = __half22float2(*(__half2*)&r.x); a[0] = t.x; a[1] = t.y;
        t = __half22float2(*(__half2*)&r.y); a[2] = t.x; a[3] = t.y;
        t = __half22float2(*(__half2*)&r.z); a[4] = t.x; a[5] = t.y;
        t = __half22float2(*(__half2*)&r.w); a[6] = t.x; a[7] = t.y;
    }

    int beg = g_rowstart[node], end = g_rowstart[node + 1];
    int j = beg;
    for (; j + 4 <= end; j += 4) {
        int s0 = g_srcidx[j], s1 = g_srcidx[j + 1], s2 = g_srcidx[j + 2], s3 = g_srcidx[j + 3];
        uint4 r0 = base[(size_t)s0 * 8 + lane8];
        uint4 r1 = base[(size_t)s1 * 8 + lane8];
        uint4 r2 = base[(size_t)s2 * 8 + lane8];
        uint4 r3 = base[(size_t)s3 * 8 + lane8];
        acc_u4(a, r0); acc_u4(a, r1); acc_u4(a, r2); acc_u4(a, r3);
    }
    for (; j < end; j++) {
        uint4 r = base[(size_t)g_srcidx[j] * 8 + lane8];
        acc_u4(a, r);
    }

    float dv = g_dinv[node];
    const float4* b24 = (const float4*)b2;
    float4 bb0 = b24[lane8 * 2], bb1 = b24[lane8 * 2 + 1];
    float4* outp = (float4*)out + (size_t)node * 16 + lane8 * 2;
    outp[0] = make_float4(fmaf(dv, a[0], bb0.x), fmaf(dv, a[1], bb0.y),
                          fmaf(dv, a[2], bb0.z), fmaf(dv, a[3], bb0.w));
    outp[1] = make_float4(fmaf(dv, a[4], bb1.x), fmaf(dv, a[5], bb1.y),
                          fmaf(dv, a[6], bb1.z), fmaf(dv, a[7], bb1.w));
}

// ---------------- launch ----------------
extern "C" void kernel_launch(void* const* d_in, const int* in_sizes, int n_in,
                              void* d_out, int out_size) {
    const float* x  = nullptr;
    const void*  ei = nullptr;
    const float* W1 = nullptr;
    const float* b1 = nullptr;
    const float* W2 = nullptr;
    const float* b2 = nullptr;
    int x_elems = 0, ei_elems = 0;

    int imax = 0, imax2 = -1;
    for (int i = 1; i < n_in; i++) if (in_sizes[i] > in_sizes[imax]) imax = i;
    for (int i = 0; i < n_in; i++) {
        if (i == imax) continue;
        if (imax2 < 0 || in_sizes[i] > in_sizes[imax2]) imax2 = i;
    }
    x  = (const float*)d_in[imax];  x_elems  = in_sizes[imax];
    ei = (const void*)d_in[imax2];  ei_elems = in_sizes[imax2];

    for (int i = 0; i < n_in; i++) {
        if (i == imax || i == imax2) continue;
        int s = in_sizes[i];
        if      (s == D_IN * D_HID)  W1 = (const float*)d_in[i];
        else if (s == D_HID)         b1 = (const float*)d_in[i];
        else if (s == D_HID * D_OUT) W2 = (const float*)d_in[i];
        else if (s == D_OUT)         b2 = (const float*)d_in[i];
    }

    float* out = (float*)d_out;
    const int n = x_elems / D_IN;
    const long long E = (long long)ei_elems / 2;
    const int n1 = n + 1;
    const int nb = (n1 + SCAN_BLK - 1) / SCAN_BLK;
    const long long Q = (E + 3) / 4;   // 4 edges per thread

    // CSR build
    k_zero_detect<<<(n + 255) / 256, 256>>>((const int*)ei, (long long)ei_elems, n);
    k_count<<<(int)((Q + 255) / 256), 256>>>(ei, E, n);
    k_scan <<<nb, SCAN_BLK>>>(n);
    k_fill <<<(int)((Q + 255) / 256), 256>>>(ei, E, n);

    // layer 1
    k_gemm1<<<(n + 127) / 128, 256>>>(x, W1, n);
    k_agg1 <<<(n + 15) / 16, 256>>>(b1, n);        // 2 nodes/warp

    // layer 2
    k_gemm2<<<(n + 127) / 128, 256>>>(W2, n);
    k_agg2 <<<(n + 31) / 32, 256>>>(b2, out, n);   // 4 nodes/warp
}